// round 3
// baseline (speedup 1.0000x reference)
#include <cuda_runtime.h>
#include <math.h>

#define BATCH 2048
#define BN_INV 0.9999950000374997f   // 1/sqrt(1+1e-5)

typedef unsigned long long u64;

#define FMA2(acc, a, b) asm("fma.rn.f32x2 %0, %1, %2, %0;" : "+l"(acc) : "l"(a), "l"(b))
__device__ __forceinline__ u64 pack2(float lo, float hi) {
    u64 r; asm("mov.b64 %0, {%1, %2};" : "=l"(r) : "f"(lo), "f"(hi)); return r;
}
__device__ __forceinline__ float2 unpack2(u64 v) {
    float2 f; asm("mov.b64 {%0, %1}, %2;" : "=f"(f.x), "=f"(f.y) : "l"(v)); return f;
}
__device__ __forceinline__ float ternv(float v, float delta, float alpha) {
    return (v > delta) ? alpha : ((v < -delta) ? -alpha : 0.f);
}

// ---------------- scratch ---------------------------------------------------
__device__ float g_h1[BATCH * 32 * 12 * 12];
__device__ float g_h2[BATCH * 1024];
__device__ float g_fc1[BATCH * 512];
__device__ u64   g_w2p[25600];     // conv2 weights, paired (oc, oc+32)

// ============================================================================
// K0: repack conv2 weights into pairs: g_w2p[(ic*25+pos)*32+ocl]
// ============================================================================
__global__ void k0_pack_w2(const float* __restrict__ w) {
    int i = blockIdx.x * 256 + threadIdx.x;
    if (i < 25600) {
        int icpos = i >> 5, ocl = i & 31;
        g_w2p[i] = pack2(w[ocl * 800 + icpos], w[(ocl + 32) * 800 + icpos]);
    }
}

// ============================================================================
// K1: conv1 + ternarize + BN + maxpool + relu. 1 CTA/sample, 384 threads.
// thread = (oy 0..23, ocl 0..15); 24 ox f32x2 accs over (ocl, ocl+16).
// Input pre-duplicated in smem -> zero pack MOVs in the hot loop.
// ============================================================================
__global__ __launch_bounds__(384) void k1_conv1(
    const float* __restrict__ x, const float* __restrict__ w,
    const float* __restrict__ bias, const float* __restrict__ bng,
    const float* __restrict__ bnb)
{
    __shared__ u64   s_in2[784];     // [28][28] dup'd
    __shared__ u64   s_w[400];       // [25 pos][16 ocl] pairs
    __shared__ u64   s_b[16];
    __shared__ float s_ex[9504];     // [(oy*12+px)][33]
    __shared__ float s_redA[16], s_redB[16], s_redC[16];

    const int tid = threadIdx.x;
    const int s = blockIdx.x;
    const int ocl = tid & 15;
    const int oy  = tid >> 4;        // 0..23

    const float* xin = x + s * 784;
    for (int i = tid; i < 784; i += 384) { const float v = xin[i]; s_in2[i] = pack2(v, v); }
    for (int i = tid; i < 400; i += 384) {
        int pos = i >> 4, oc2 = i & 15;
        s_w[i] = pack2(w[oc2 * 25 + pos], w[(oc2 + 16) * 25 + pos]);
    }
    if (tid < 16) s_b[tid] = pack2(bias[tid], bias[tid + 16]);
    __syncthreads();

    u64 acc[24];
    {
        const u64 bb = s_b[ocl];
        #pragma unroll
        for (int p = 0; p < 24; p++) acc[p] = bb;
    }

    #pragma unroll
    for (int ky = 0; ky < 5; ky++) {
        const u64* rp = s_in2 + (oy + ky) * 28;
        u64 rowv[28];
        #pragma unroll
        for (int c = 0; c < 28; c++) rowv[c] = rp[c];
        #pragma unroll
        for (int kx = 0; kx < 5; kx++) {
            const u64 wv = s_w[(ky * 5 + kx) * 16 + ocl];
            #pragma unroll
            for (int p = 0; p < 24; p++) FMA2(acc[p], rowv[p + kx], wv);
        }
    }

    // per-sample ternarize stats over 18432 values (1-sync reductions)
    const int lane = tid & 31, wid = tid >> 5;
    float sa = 0.f;
    #pragma unroll
    for (int p = 0; p < 24; p++) {
        const float2 t = unpack2(acc[p]);
        sa += fabsf(t.x) + fabsf(t.y);
    }
    #pragma unroll
    for (int o = 16; o > 0; o >>= 1) sa += __shfl_down_sync(0xffffffffu, sa, o);
    if (lane == 0) s_redA[wid] = sa;
    __syncthreads();
    float tot = 0.f;
    #pragma unroll
    for (int wk = 0; wk < 12; wk++) tot += s_redA[wk];
    const float delta = 0.7f * tot / 18432.f;

    float ms = 0.f, ct = 0.f;
    #pragma unroll
    for (int p = 0; p < 24; p++) {
        const float2 t = unpack2(acc[p]);
        float a = fabsf(t.x); if (a > delta) { ms += a; ct += 1.f; }
        a = fabsf(t.y);       if (a > delta) { ms += a; ct += 1.f; }
    }
    #pragma unroll
    for (int o = 16; o > 0; o >>= 1) {
        ms += __shfl_down_sync(0xffffffffu, ms, o);
        ct += __shfl_down_sync(0xffffffffu, ct, o);
    }
    if (lane == 0) { s_redB[wid] = ms; s_redC[wid] = ct; }
    __syncthreads();
    float mtot = 0.f, ctot = 0.f;
    #pragma unroll
    for (int wk = 0; wk < 12; wk++) { mtot += s_redB[wk]; ctot += s_redC[wk]; }
    const float alpha = mtot / ctot;

    const float g0 = bng[ocl] * BN_INV, b0 = bnb[ocl];
    const float g1 = bng[ocl + 16] * BN_INV, b1 = bnb[ocl + 16];

    // ternarize + BN + pool-x -> s_ex
    #pragma unroll
    for (int p = 0; p < 12; p++) {
        const float2 ta = unpack2(acc[2 * p]);
        const float2 tb = unpack2(acc[2 * p + 1]);
        const float mlo = fmaxf(fmaf(ternv(ta.x, delta, alpha), g0, b0),
                                fmaf(ternv(tb.x, delta, alpha), g0, b0));
        const float mhi = fmaxf(fmaf(ternv(ta.y, delta, alpha), g1, b1),
                                fmaf(ternv(tb.y, delta, alpha), g1, b1));
        s_ex[(oy * 12 + p) * 33 + ocl]      = mlo;
        s_ex[(oy * 12 + p) * 33 + ocl + 16] = mhi;
    }
    __syncthreads();

    // pool-y + relu -> g_h1 [s][32][12][12]
    for (int i = tid; i < 4608; i += 384) {
        const int oc = i / 144, r = i % 144, py = r / 12, px = r % 12;
        const float m = fmaxf(s_ex[((2 * py) * 12 + px) * 33 + oc],
                              s_ex[((2 * py + 1) * 12 + px) * 33 + oc]);
        g_h1[s * 4608 + i] = fmaxf(m, 0.f);
    }
}

// ============================================================================
// K2: conv2 + ternarize + BN + maxpool + relu. PERSISTENT, 512 threads.
// Weights (204.8KB paired) in smem once; 5 barriers/sample.
// ============================================================================
#define K2_SMEM (25600 * 8 + (4608 + 2080 + 48) * 4)

__global__ __launch_bounds__(512) void k2_conv2(
    const float* __restrict__ bias, const float* __restrict__ bng,
    const float* __restrict__ bnb)
{
    extern __shared__ char smraw[];
    u64*   s_w    = (u64*)smraw;                      // 25600 pairs
    float* s_in   = (float*)(smraw + 25600 * 8);      // 4608
    float* s_ex   = s_in + 4608;                      // [32][65]
    float* s_redA = s_ex + 2080;                      // 16
    float* s_redB = s_redA + 16;                      // 16
    float* s_redC = s_redB + 16;                      // 16

    const int tid = threadIdx.x;
    const int lane = tid & 31, wid = tid >> 5;
    const int ocl = tid & 31;
    const int xh  = (tid >> 5) & 1;
    const int oy  = tid >> 6;        // 0..7, warp-uniform

    for (int i = tid; i < 25600; i += 512) s_w[i] = g_w2p[i];

    const u64 bb = pack2(bias[ocl], bias[ocl + 32]);
    const float g0 = bng[ocl] * BN_INV, b0 = bnb[ocl];
    const float g1 = bng[ocl + 32] * BN_INV, b1 = bnb[ocl + 32];

    for (int s = blockIdx.x; s < BATCH; s += gridDim.x) {
        __syncthreads();   // s_in/s_ex safe to overwrite
        const float* hin = g_h1 + s * 4608;
        for (int i = tid; i < 4608; i += 512) s_in[i] = hin[i];
        __syncthreads();

        u64 acc[4];
        #pragma unroll
        for (int j = 0; j < 4; j++) acc[j] = bb;

        for (int ic = 0; ic < 32; ic++) {
            #pragma unroll
            for (int ky = 0; ky < 5; ky++) {
                const float* rp = s_in + ic * 144 + (oy + ky) * 12 + xh * 4;
                const float4 q0 = *(const float4*)(rp);
                const float4 q1 = *(const float4*)(rp + 4);
                u64 rp2[8];
                rp2[0] = pack2(q0.x, q0.x); rp2[1] = pack2(q0.y, q0.y);
                rp2[2] = pack2(q0.z, q0.z); rp2[3] = pack2(q0.w, q0.w);
                rp2[4] = pack2(q1.x, q1.x); rp2[5] = pack2(q1.y, q1.y);
                rp2[6] = pack2(q1.z, q1.z); rp2[7] = pack2(q1.w, q1.w);
                #pragma unroll
                for (int kx = 0; kx < 5; kx++) {
                    const u64 wv = s_w[(ic * 25 + ky * 5 + kx) * 32 + ocl];
                    #pragma unroll
                    for (int j = 0; j < 4; j++) FMA2(acc[j], rp2[j + kx], wv);
                }
            }
        }

        // ternarize stats over 4096 values (1-sync reductions)
        float sa = 0.f;
        #pragma unroll
        for (int j = 0; j < 4; j++) {
            const float2 t = unpack2(acc[j]);
            sa += fabsf(t.x) + fabsf(t.y);
        }
        #pragma unroll
        for (int o = 16; o > 0; o >>= 1) sa += __shfl_down_sync(0xffffffffu, sa, o);
        if (lane == 0) s_redA[wid] = sa;
        __syncthreads();
        float tot = 0.f;
        #pragma unroll
        for (int wk = 0; wk < 16; wk++) tot += s_redA[wk];
        const float delta = 0.7f * tot / 4096.f;

        float ms = 0.f, ct = 0.f;
        #pragma unroll
        for (int j = 0; j < 4; j++) {
            const float2 t = unpack2(acc[j]);
            float a = fabsf(t.x); if (a > delta) { ms += a; ct += 1.f; }
            a = fabsf(t.y);       if (a > delta) { ms += a; ct += 1.f; }
        }
        #pragma unroll
        for (int o = 16; o > 0; o >>= 1) {
            ms += __shfl_down_sync(0xffffffffu, ms, o);
            ct += __shfl_down_sync(0xffffffffu, ct, o);
        }
        if (lane == 0) { s_redB[wid] = ms; s_redC[wid] = ct; }
        __syncthreads();
        float mtot = 0.f, ctot = 0.f;
        #pragma unroll
        for (int wk = 0; wk < 16; wk++) { mtot += s_redB[wk]; ctot += s_redC[wk]; }
        const float alpha = mtot / ctot;

        // ternarize + BN + pool-x -> s_ex
        #pragma unroll
        for (int p = 0; p < 2; p++) {
            const float2 ta = unpack2(acc[2 * p]);
            const float2 tb = unpack2(acc[2 * p + 1]);
            const float mlo = fmaxf(fmaf(ternv(ta.x, delta, alpha), g0, b0),
                                    fmaf(ternv(tb.x, delta, alpha), g0, b0));
            const float mhi = fmaxf(fmaf(ternv(ta.y, delta, alpha), g1, b1),
                                    fmaf(ternv(tb.y, delta, alpha), g1, b1));
            const int px = xh * 2 + p;
            s_ex[(oy * 4 + px) * 65 + ocl]      = mlo;
            s_ex[(oy * 4 + px) * 65 + ocl + 32] = mhi;
        }
        __syncthreads();

        // pool-y + relu -> g_h2 [s][1024]
        for (int i = tid; i < 1024; i += 512) {
            const int oc = i >> 4, r = i & 15, py = r >> 2, px = r & 3;
            const float m = fmaxf(s_ex[((2 * py) * 4 + px) * 65 + oc],
                                  s_ex[((2 * py + 1) * 4 + px) * 65 + oc]);
            g_h2[s * 1024 + i] = fmaxf(m, 0.f);
        }
    }
}

// ============================================================================
// K3: fc1 GEMM, 64x64 tile, double-buffered, dup'd As2 (no a-side MOVs)
// ============================================================================
__global__ __launch_bounds__(256) void k3_fc1(
    const float* __restrict__ Wf, const float* __restrict__ bf)
{
    __shared__ u64   As2[2][16][64];   // dup'd a: (a,a) per m
    __shared__ float Bs [2][16][68];

    const int tid = threadIdx.x;
    const int tx = tid & 15, ty = tid >> 4;
    const int bn = blockIdx.x, bm = blockIdx.y;

    const float* Ap = g_h2 + (size_t)(bm * 64) * 1024;
    const float* Bp = Wf   + (size_t)(bn * 64) * 1024;

    const int lr = tid >> 2;            // row 0..63
    const int lk = (tid & 3) * 4;       // k 0,4,8,12

    u64 acc[4][2];
    #pragma unroll
    for (int i = 0; i < 4; i++) { acc[i][0] = 0ull; acc[i][1] = 0ull; }

    // prologue: tile 0
    {
        const float4 a = *(const float4*)(Ap + lr * 1024 + lk);
        const float4 b = *(const float4*)(Bp + lr * 1024 + lk);
        As2[0][lk + 0][lr] = pack2(a.x, a.x); As2[0][lk + 1][lr] = pack2(a.y, a.y);
        As2[0][lk + 2][lr] = pack2(a.z, a.z); As2[0][lk + 3][lr] = pack2(a.w, a.w);
        Bs[0][lk + 0][lr] = b.x; Bs[0][lk + 1][lr] = b.y;
        Bs[0][lk + 2][lr] = b.z; Bs[0][lk + 3][lr] = b.w;
    }
    __syncthreads();

    for (int t = 0; t < 64; t++) {
        const int cur = t & 1;
        float4 an, bn4;
        if (t < 63) {
            an  = *(const float4*)(Ap + lr * 1024 + (t + 1) * 16 + lk);
            bn4 = *(const float4*)(Bp + lr * 1024 + (t + 1) * 16 + lk);
        }
        #pragma unroll
        for (int kk = 0; kk < 16; kk++) {
            const ulonglong2 av01 = *(const ulonglong2*)&As2[cur][kk][ty * 4];
            const ulonglong2 av23 = *(const ulonglong2*)&As2[cur][kk][ty * 4 + 2];
            const float4 bv = *(const float4*)(&Bs[cur][kk][tx * 4]);
            const u64 bp0 = pack2(bv.x, bv.y);
            const u64 bp1 = pack2(bv.z, bv.w);
            FMA2(acc[0][0], av01.x, bp0); FMA2(acc[0][1], av01.x, bp1);
            FMA2(acc[1][0], av01.y, bp0); FMA2(acc[1][1], av01.y, bp1);
            FMA2(acc[2][0], av23.x, bp0); FMA2(acc[2][1], av23.x, bp1);
            FMA2(acc[3][0], av23.y, bp0); FMA2(acc[3][1], av23.y, bp1);
        }
        if (t < 63) {
            const int nxt = cur ^ 1;
            As2[nxt][lk + 0][lr] = pack2(an.x, an.x); As2[nxt][lk + 1][lr] = pack2(an.y, an.y);
            As2[nxt][lk + 2][lr] = pack2(an.z, an.z); As2[nxt][lk + 3][lr] = pack2(an.w, an.w);
            Bs[nxt][lk + 0][lr] = bn4.x; Bs[nxt][lk + 1][lr] = bn4.y;
            Bs[nxt][lk + 2][lr] = bn4.z; Bs[nxt][lk + 3][lr] = bn4.w;
        }
        __syncthreads();
    }

    const int n0 = bn * 64 + tx * 4;
    const float4 bia = *(const float4*)(bf + n0);
    #pragma unroll
    for (int i = 0; i < 4; i++) {
        const int m = bm * 64 + ty * 4 + i;
        const float2 r0 = unpack2(acc[i][0]);
        const float2 r1 = unpack2(acc[i][1]);
        float4 o;
        o.x = r0.x + bia.x; o.y = r0.y + bia.y;
        o.z = r1.x + bia.z; o.w = r1.y + bia.w;
        *(float4*)(g_fc1 + (size_t)m * 512 + n0) = o;
    }
}

// ============================================================================
// K4: ternarize(512)+relu + fc2 + ternarize(10). 1 warp/sample.
// ============================================================================
__global__ __launch_bounds__(256) void k4_fc2(
    const float* __restrict__ W2, const float* __restrict__ b2,
    float* __restrict__ out)
{
    __shared__ float s_w2[5120];
    __shared__ float s_b2[10];

    const int tid = threadIdx.x;
    for (int i = tid; i < 5120; i += 256) s_w2[i] = W2[i];
    if (tid < 10) s_b2[tid] = b2[tid];
    __syncthreads();

    const int lane = tid & 31, warp = tid >> 5;
    const int s = blockIdx.x * 8 + warp;
    const float* hr = g_fc1 + (size_t)s * 512;

    float h[16];
    #pragma unroll
    for (int k = 0; k < 16; k++) h[k] = hr[lane + 32 * k];

    float sa = 0.f;
    #pragma unroll
    for (int k = 0; k < 16; k++) sa += fabsf(h[k]);
    #pragma unroll
    for (int o = 16; o > 0; o >>= 1) sa += __shfl_xor_sync(0xffffffffu, sa, o);
    const float delta = 0.7f * sa / 512.f;

    float ms = 0.f, ct = 0.f;
    #pragma unroll
    for (int k = 0; k < 16; k++) {
        const float a = fabsf(h[k]);
        if (a > delta) { ms += a; ct += 1.f; }
    }
    #pragma unroll
    for (int o = 16; o > 0; o >>= 1) {
        ms += __shfl_xor_sync(0xffffffffu, ms, o);
        ct += __shfl_xor_sync(0xffffffffu, ct, o);
    }
    const float alpha = ms / ct;

    #pragma unroll
    for (int k = 0; k < 16; k++) h[k] = fmaxf(ternv(h[k], delta, alpha), 0.f);

    float pj[10];
    #pragma unroll
    for (int j = 0; j < 10; j++) {
        float p = 0.f;
        #pragma unroll
        for (int k = 0; k < 16; k++)
            p = fmaf(h[k], s_w2[j * 512 + lane + 32 * k], p);
        #pragma unroll
        for (int o = 16; o > 0; o >>= 1) p += __shfl_xor_sync(0xffffffffu, p, o);
        pj[j] = p + s_b2[j];
    }

    float sa2 = 0.f;
    #pragma unroll
    for (int j = 0; j < 10; j++) sa2 += fabsf(pj[j]);
    const float d2 = 0.7f * sa2 / 10.f;
    float ms2 = 0.f, c2 = 0.f;
    #pragma unroll
    for (int j = 0; j < 10; j++) {
        const float a = fabsf(pj[j]);
        if (a > d2) { ms2 += a; c2 += 1.f; }
    }
    const float al2 = ms2 / c2;

    if (lane < 10) {
        float v = 0.f;
        #pragma unroll
        for (int j = 0; j < 10; j++) if (lane == j) v = pj[j];
        out[(size_t)s * 10 + lane] = (v > d2) ? al2 : ((v < -d2) ? -al2 : 0.f);
    }
}

// ============================================================================
extern "C" void kernel_launch(void* const* d_in, const int* in_sizes, int n_in,
                              void* d_out, int out_size)
{
    const float* x       = (const float*)d_in[0];
    const float* conv1_w = (const float*)d_in[1];
    const float* conv1_b = (const float*)d_in[2];
    const float* bn1_g   = (const float*)d_in[3];
    const float* bn1_b   = (const float*)d_in[4];
    const float* conv2_w = (const float*)d_in[5];
    const float* conv2_b = (const float*)d_in[6];
    const float* bn2_g   = (const float*)d_in[7];
    const float* bn2_b   = (const float*)d_in[8];
    const float* fc1_w   = (const float*)d_in[9];
    const float* fc1_b   = (const float*)d_in[10];
    const float* fc2_w   = (const float*)d_in[11];
    const float* fc2_b   = (const float*)d_in[12];
    float* out = (float*)d_out;

    int nsm = 148;
    cudaDeviceGetAttribute(&nsm, cudaDevAttrMultiProcessorCount, 0);
    if (nsm <= 0) nsm = 148;

    cudaFuncSetAttribute(k2_conv2, cudaFuncAttributeMaxDynamicSharedMemorySize, K2_SMEM);

    k0_pack_w2<<<100, 256>>>(conv2_w);
    k1_conv1<<<BATCH, 384>>>(x, conv1_w, conv1_b, bn1_g, bn1_b);
    k2_conv2<<<nsm, 512, K2_SMEM>>>(conv2_b, bn2_g, bn2_b);
    k3_fc1<<<dim3(8, 32), 256>>>(fc1_w, fc1_b);
    k4_fc2<<<256, 256>>>(fc2_w, fc2_b, out);
}

// round 4
// speedup vs baseline: 1.2094x; 1.2094x over previous
#include <cuda_runtime.h>
#include <math.h>

#define BATCH 2048
#define BN_INV 0.9999950000374997f   // 1/sqrt(1+1e-5)

typedef unsigned long long u64;

#define FMA2(acc, a, b) asm("fma.rn.f32x2 %0, %1, %2, %0;" : "+l"(acc) : "l"(a), "l"(b))
__device__ __forceinline__ u64 pack2(float lo, float hi) {
    u64 r; asm("mov.b64 %0, {%1, %2};" : "=l"(r) : "f"(lo), "f"(hi)); return r;
}
__device__ __forceinline__ float2 unpack2(u64 v) {
    float2 f; asm("mov.b64 {%0, %1}, %2;" : "=f"(f.x), "=f"(f.y) : "l"(v)); return f;
}
__device__ __forceinline__ float ternv(float v, float delta, float alpha) {
    return (v > delta) ? alpha : ((v < -delta) ? -alpha : 0.f);
}

// ---------------- scratch ---------------------------------------------------
__device__ float g_h1[BATCH * 32 * 12 * 12];
__device__ float g_h2[BATCH * 1024];
__device__ float g_fc1[BATCH * 512];
__device__ u64   g_w2p[25600];     // conv2 weights, paired (oc, oc+32)

// ---------------- block reductions (r2 versions) -----------------------------
__device__ __forceinline__ float block_reduce(float v, float* s_red, int tid, int nthr) {
    #pragma unroll
    for (int o = 16; o > 0; o >>= 1) v += __shfl_down_sync(0xffffffffu, v, o);
    int wid = tid >> 5, lane = tid & 31, nw = nthr >> 5;
    __syncthreads();
    if (lane == 0) s_red[wid] = v;
    __syncthreads();
    if (wid == 0) {
        float x = (lane < nw) ? s_red[lane] : 0.f;
        #pragma unroll
        for (int o = 16; o > 0; o >>= 1) x += __shfl_down_sync(0xffffffffu, x, o);
        if (lane == 0) s_red[0] = x;
    }
    __syncthreads();
    return s_red[0];
}

__device__ __forceinline__ float2 block_reduce2(float a, float b, float* s_red, int tid, int nthr) {
    #pragma unroll
    for (int o = 16; o > 0; o >>= 1) {
        a += __shfl_down_sync(0xffffffffu, a, o);
        b += __shfl_down_sync(0xffffffffu, b, o);
    }
    int wid = tid >> 5, lane = tid & 31, nw = nthr >> 5;
    __syncthreads();
    if (lane == 0) { s_red[wid] = a; s_red[32 + wid] = b; }
    __syncthreads();
    if (wid == 0) {
        float x = (lane < nw) ? s_red[lane] : 0.f;
        float y = (lane < nw) ? s_red[32 + lane] : 0.f;
        #pragma unroll
        for (int o = 16; o > 0; o >>= 1) {
            x += __shfl_down_sync(0xffffffffu, x, o);
            y += __shfl_down_sync(0xffffffffu, y, o);
        }
        if (lane == 0) { s_red[0] = x; s_red[32] = y; }
    }
    __syncthreads();
    float2 r; r.x = s_red[0]; r.y = s_red[32];
    return r;
}

// ============================================================================
// K0: repack conv2 weights into pairs: g_w2p[(ic*25+pos)*32+ocl]
// ============================================================================
__global__ void k0_pack_w2(const float* __restrict__ w) {
    int i = blockIdx.x * 256 + threadIdx.x;
    if (i < 25600) {
        int icpos = i >> 5, ocl = i & 31;
        g_w2p[i] = pack2(w[ocl * 800 + icpos], w[(ocl + 32) * 800 + icpos]);
    }
}

// ============================================================================
// K1: conv1 + ternarize + BN + maxpool + relu. (round-2 version, best so far)
// 1 CTA/sample, 384 threads; thread = (oy 0..23, ocl 0..15).
// ============================================================================
__global__ __launch_bounds__(384) void k1_conv1(
    const float* __restrict__ x, const float* __restrict__ w,
    const float* __restrict__ bias, const float* __restrict__ bng,
    const float* __restrict__ bnb)
{
    __shared__ float s_in[784];      // [28][28]
    __shared__ u64   s_w[400];       // [25 pos][16 ocl] pairs
    __shared__ u64   s_b[16];
    __shared__ float s_ex[9504];     // [(oy*12+px)][33]
    __shared__ float s_red[64];

    const int tid = threadIdx.x;
    const int s = blockIdx.x;
    const int ocl = tid & 15;
    const int oy  = tid >> 4;        // 0..23

    const float* xin = x + s * 784;
    for (int i = tid; i < 784; i += 384) s_in[i] = xin[i];
    for (int i = tid; i < 400; i += 384) {
        int pos = i >> 4, oc2 = i & 15;
        s_w[i] = pack2(w[oc2 * 25 + pos], w[(oc2 + 16) * 25 + pos]);
    }
    if (tid < 16) s_b[tid] = pack2(bias[tid], bias[tid + 16]);
    __syncthreads();

    u64 acc[24];
    {
        const u64 bb = s_b[ocl];
        #pragma unroll
        for (int p = 0; p < 24; p++) acc[p] = bb;
    }

    #pragma unroll
    for (int ky = 0; ky < 5; ky++) {
        const float* rp = s_in + (oy + ky) * 28;
        u64 rp2[28];
        #pragma unroll
        for (int t = 0; t < 7; t++) {
            const float4 q = *(const float4*)(rp + t * 4);
            rp2[t * 4 + 0] = pack2(q.x, q.x);
            rp2[t * 4 + 1] = pack2(q.y, q.y);
            rp2[t * 4 + 2] = pack2(q.z, q.z);
            rp2[t * 4 + 3] = pack2(q.w, q.w);
        }
        #pragma unroll
        for (int kx = 0; kx < 5; kx++) {
            const u64 wv = s_w[(ky * 5 + kx) * 16 + ocl];
            #pragma unroll
            for (int p = 0; p < 24; p++) FMA2(acc[p], rp2[p + kx], wv);
        }
    }

    float sa = 0.f;
    #pragma unroll
    for (int p = 0; p < 24; p++) {
        const float2 t = unpack2(acc[p]);
        sa += fabsf(t.x) + fabsf(t.y);
    }
    const float tot = block_reduce(sa, s_red, tid, 384);
    const float delta = 0.7f * tot / 18432.f;

    float ms = 0.f, ct = 0.f;
    #pragma unroll
    for (int p = 0; p < 24; p++) {
        const float2 t = unpack2(acc[p]);
        float a = fabsf(t.x); if (a > delta) { ms += a; ct += 1.f; }
        a = fabsf(t.y);       if (a > delta) { ms += a; ct += 1.f; }
    }
    const float2 mc = block_reduce2(ms, ct, s_red, tid, 384);
    const float alpha = mc.x / mc.y;

    const float g0 = bng[ocl] * BN_INV, b0 = bnb[ocl];
    const float g1 = bng[ocl + 16] * BN_INV, b1 = bnb[ocl + 16];

    #pragma unroll
    for (int p = 0; p < 12; p++) {
        const float2 ta = unpack2(acc[2 * p]);
        const float2 tb = unpack2(acc[2 * p + 1]);
        const float mlo = fmaxf(fmaf(ternv(ta.x, delta, alpha), g0, b0),
                                fmaf(ternv(tb.x, delta, alpha), g0, b0));
        const float mhi = fmaxf(fmaf(ternv(ta.y, delta, alpha), g1, b1),
                                fmaf(ternv(tb.y, delta, alpha), g1, b1));
        s_ex[(oy * 12 + p) * 33 + ocl]      = mlo;
        s_ex[(oy * 12 + p) * 33 + ocl + 16] = mhi;
    }
    __syncthreads();

    for (int i = tid; i < 4608; i += 384) {
        const int oc = i / 144, r = i % 144, py = r / 12, px = r % 12;
        const float m = fmaxf(s_ex[((2 * py) * 12 + px) * 33 + oc],
                              s_ex[((2 * py + 1) * 12 + px) * 33 + oc]);
        g_h1[s * 4608 + i] = fmaxf(m, 0.f);
    }
}

// ============================================================================
// K2: conv2 + ternarize + BN + maxpool + relu. PERSISTENT, 256 threads.
// thread = (oy 0..7, ocl 0..31), FULL 8-wide output row per thread:
// 40 FMA2 per weight fetch -> crossbar no longer binding.
// s_ex aliases s_in (disjoint in time). smem = 223424 B.
// ============================================================================
#define K2_SMEM (25600 * 8 + 4608 * 4 + 48 * 4)

__global__ __launch_bounds__(256) void k2_conv2(
    const float* __restrict__ bias, const float* __restrict__ bng,
    const float* __restrict__ bnb)
{
    extern __shared__ char smraw[];
    u64*   s_w    = (u64*)smraw;                      // 25600 pairs (204800 B)
    float* s_in   = (float*)(smraw + 25600 * 8);      // 4608 floats
    float* s_ex   = s_in;                             // alias: [32][65] used after conv
    float* s_redA = (float*)(smraw + 25600 * 8 + 4608 * 4);   // 16
    float* s_redB = s_redA + 16;
    float* s_redC = s_redB + 16;

    const int tid = threadIdx.x;
    const int lane = tid & 31, wid = tid >> 5;
    const int ocl = tid & 31;
    const int oy  = tid >> 5;        // 0..7, warp-uniform

    for (int i = tid; i < 25600; i += 256) s_w[i] = g_w2p[i];

    const u64 bb = pack2(bias[ocl], bias[ocl + 32]);
    const float g0 = bng[ocl] * BN_INV, b0 = bnb[ocl];
    const float g1 = bng[ocl + 32] * BN_INV, b1 = bnb[ocl + 32];

    for (int s = blockIdx.x; s < BATCH; s += gridDim.x) {
        __syncthreads();   // s_in/s_ex safe to overwrite
        {
            const float4* hin = (const float4*)(g_h1 + s * 4608);
            float4* si4 = (float4*)s_in;
            for (int i = tid; i < 1152; i += 256) si4[i] = hin[i];
        }
        __syncthreads();

        u64 acc[8];
        #pragma unroll
        for (int j = 0; j < 8; j++) acc[j] = bb;

        for (int ic = 0; ic < 32; ic++) {
            #pragma unroll
            for (int ky = 0; ky < 5; ky++) {
                const float* rp = s_in + ic * 144 + (oy + ky) * 12;
                const float4 q0 = *(const float4*)(rp);
                const float4 q1 = *(const float4*)(rp + 4);
                const float4 q2 = *(const float4*)(rp + 8);
                u64 rw[12];
                rw[0]  = pack2(q0.x, q0.x); rw[1]  = pack2(q0.y, q0.y);
                rw[2]  = pack2(q0.z, q0.z); rw[3]  = pack2(q0.w, q0.w);
                rw[4]  = pack2(q1.x, q1.x); rw[5]  = pack2(q1.y, q1.y);
                rw[6]  = pack2(q1.z, q1.z); rw[7]  = pack2(q1.w, q1.w);
                rw[8]  = pack2(q2.x, q2.x); rw[9]  = pack2(q2.y, q2.y);
                rw[10] = pack2(q2.z, q2.z); rw[11] = pack2(q2.w, q2.w);
                const u64* wrow = s_w + (ic * 25 + ky * 5) * 32 + ocl;
                #pragma unroll
                for (int kx = 0; kx < 5; kx++) {
                    const u64 wv = wrow[kx * 32];
                    #pragma unroll
                    for (int j = 0; j < 8; j++) FMA2(acc[j], rw[j + kx], wv);
                }
            }
        }

        // ternarize stats over 4096 values (8 warps)
        float sa = 0.f;
        #pragma unroll
        for (int j = 0; j < 8; j++) {
            const float2 t = unpack2(acc[j]);
            sa += fabsf(t.x) + fabsf(t.y);
        }
        #pragma unroll
        for (int o = 16; o > 0; o >>= 1) sa += __shfl_down_sync(0xffffffffu, sa, o);
        if (lane == 0) s_redA[wid] = sa;
        __syncthreads();
        float tot = 0.f;
        #pragma unroll
        for (int wk = 0; wk < 8; wk++) tot += s_redA[wk];
        const float delta = 0.7f * tot / 4096.f;

        float ms = 0.f, ct = 0.f;
        #pragma unroll
        for (int j = 0; j < 8; j++) {
            const float2 t = unpack2(acc[j]);
            float a = fabsf(t.x); if (a > delta) { ms += a; ct += 1.f; }
            a = fabsf(t.y);       if (a > delta) { ms += a; ct += 1.f; }
        }
        #pragma unroll
        for (int o = 16; o > 0; o >>= 1) {
            ms += __shfl_down_sync(0xffffffffu, ms, o);
            ct += __shfl_down_sync(0xffffffffu, ct, o);
        }
        if (lane == 0) { s_redB[wid] = ms; s_redC[wid] = ct; }
        __syncthreads();     // also orders: all s_in reads done before s_ex writes
        float mtot = 0.f, ctot = 0.f;
        #pragma unroll
        for (int wk = 0; wk < 8; wk++) { mtot += s_redB[wk]; ctot += s_redC[wk]; }
        const float alpha = mtot / ctot;

        // ternarize + BN + pool-x -> s_ex [32 rows (oy*4+px)][65]
        #pragma unroll
        for (int p = 0; p < 4; p++) {
            const float2 ta = unpack2(acc[2 * p]);
            const float2 tb = unpack2(acc[2 * p + 1]);
            const float mlo = fmaxf(fmaf(ternv(ta.x, delta, alpha), g0, b0),
                                    fmaf(ternv(tb.x, delta, alpha), g0, b0));
            const float mhi = fmaxf(fmaf(ternv(ta.y, delta, alpha), g1, b1),
                                    fmaf(ternv(tb.y, delta, alpha), g1, b1));
            s_ex[(oy * 4 + p) * 65 + ocl]      = mlo;
            s_ex[(oy * 4 + p) * 65 + ocl + 32] = mhi;
        }
        __syncthreads();

        // pool-y + relu -> g_h2 [s][1024]  (layout oc*16 + py*4 + px)
        for (int i = tid; i < 1024; i += 256) {
            const int oc = i >> 4, r = i & 15, py = r >> 2, px = r & 3;
            const float m = fmaxf(s_ex[((2 * py) * 4 + px) * 65 + oc],
                                  s_ex[((2 * py + 1) * 4 + px) * 65 + oc]);
            g_h2[s * 1024 + i] = fmaxf(m, 0.f);
        }
    }
}

// ============================================================================
// K3: fc1 GEMM. 64x64 tile, 128 threads, 8m x 4n microtile.
// A-side LDS is warp-broadcast (2 distinct addrs/warp) -> crossbar unbound.
// ============================================================================
__global__ __launch_bounds__(128) void k3_fc1(
    const float* __restrict__ Wf, const float* __restrict__ bf)
{
    __shared__ float As[16][68];
    __shared__ float Bs[16][68];

    const int tid = threadIdx.x;
    const int tn = tid & 15;       // n-group 0..15 (n = tn*4)
    const int tm = tid >> 4;       // m-group 0..7  (m = tm*8)
    const int bn = blockIdx.x, bm = blockIdx.y;

    const float* Ap = g_h2 + (size_t)(bm * 64) * 1024;
    const float* Bp = Wf   + (size_t)(bn * 64) * 1024;

    const int lr = tid >> 1;           // row 0..63
    const int lk = (tid & 1) * 8;      // k offset 0 or 8

    u64 acc[8][2];
    #pragma unroll
    for (int i = 0; i < 8; i++) { acc[i][0] = 0ull; acc[i][1] = 0ull; }

    for (int k0 = 0; k0 < 1024; k0 += 16) {
        const float4 a0 = *(const float4*)(Ap + lr * 1024 + k0 + lk);
        const float4 a1 = *(const float4*)(Ap + lr * 1024 + k0 + lk + 4);
        const float4 b0 = *(const float4*)(Bp + lr * 1024 + k0 + lk);
        const float4 b1 = *(const float4*)(Bp + lr * 1024 + k0 + lk + 4);
        __syncthreads();
        As[lk + 0][lr] = a0.x; As[lk + 1][lr] = a0.y;
        As[lk + 2][lr] = a0.z; As[lk + 3][lr] = a0.w;
        As[lk + 4][lr] = a1.x; As[lk + 5][lr] = a1.y;
        As[lk + 6][lr] = a1.z; As[lk + 7][lr] = a1.w;
        Bs[lk + 0][lr] = b0.x; Bs[lk + 1][lr] = b0.y;
        Bs[lk + 2][lr] = b0.z; Bs[lk + 3][lr] = b0.w;
        Bs[lk + 4][lr] = b1.x; Bs[lk + 5][lr] = b1.y;
        Bs[lk + 6][lr] = b1.z; Bs[lk + 7][lr] = b1.w;
        __syncthreads();
        #pragma unroll
        for (int kk = 0; kk < 16; kk++) {
            const float4 av0 = *(const float4*)(&As[kk][tm * 8]);
            const float4 av1 = *(const float4*)(&As[kk][tm * 8 + 4]);
            const float4 bv  = *(const float4*)(&Bs[kk][tn * 4]);
            const u64 bp0 = pack2(bv.x, bv.y);
            const u64 bp1 = pack2(bv.z, bv.w);
            u64 am[8];
            am[0] = pack2(av0.x, av0.x); am[1] = pack2(av0.y, av0.y);
            am[2] = pack2(av0.z, av0.z); am[3] = pack2(av0.w, av0.w);
            am[4] = pack2(av1.x, av1.x); am[5] = pack2(av1.y, av1.y);
            am[6] = pack2(av1.z, av1.z); am[7] = pack2(av1.w, av1.w);
            #pragma unroll
            for (int i = 0; i < 8; i++) {
                FMA2(acc[i][0], am[i], bp0);
                FMA2(acc[i][1], am[i], bp1);
            }
        }
    }

    const int n0 = bn * 64 + tn * 4;
    const float4 bia = *(const float4*)(bf + n0);
    #pragma unroll
    for (int i = 0; i < 8; i++) {
        const int m = bm * 64 + tm * 8 + i;
        const float2 r0 = unpack2(acc[i][0]);
        const float2 r1 = unpack2(acc[i][1]);
        float4 o;
        o.x = r0.x + bia.x; o.y = r0.y + bia.y;
        o.z = r1.x + bia.z; o.w = r1.y + bia.w;
        *(float4*)(g_fc1 + (size_t)m * 512 + n0) = o;
    }
}

// ============================================================================
// K4: ternarize(512)+relu + fc2 + ternarize(10). 1 warp/sample. (r2 version)
// ============================================================================
__global__ __launch_bounds__(256) void k4_fc2(
    const float* __restrict__ W2, const float* __restrict__ b2,
    float* __restrict__ out)
{
    __shared__ float s_w2[5120];
    __shared__ float s_b2[10];

    const int tid = threadIdx.x;
    for (int i = tid; i < 5120; i += 256) s_w2[i] = W2[i];
    if (tid < 10) s_b2[tid] = b2[tid];
    __syncthreads();

    const int lane = tid & 31, warp = tid >> 5;
    const int s = blockIdx.x * 8 + warp;
    const float* hr = g_fc1 + (size_t)s * 512;

    float h[16];
    #pragma unroll
    for (int k = 0; k < 16; k++) h[k] = hr[lane + 32 * k];

    float sa = 0.f;
    #pragma unroll
    for (int k = 0; k < 16; k++) sa += fabsf(h[k]);
    #pragma unroll
    for (int o = 16; o > 0; o >>= 1) sa += __shfl_xor_sync(0xffffffffu, sa, o);
    const float delta = 0.7f * sa / 512.f;

    float ms = 0.f, ct = 0.f;
    #pragma unroll
    for (int k = 0; k < 16; k++) {
        const float a = fabsf(h[k]);
        if (a > delta) { ms += a; ct += 1.f; }
    }
    #pragma unroll
    for (int o = 16; o > 0; o >>= 1) {
        ms += __shfl_xor_sync(0xffffffffu, ms, o);
        ct += __shfl_xor_sync(0xffffffffu, ct, o);
    }
    const float alpha = ms / ct;

    #pragma unroll
    for (int k = 0; k < 16; k++) h[k] = fmaxf(ternv(h[k], delta, alpha), 0.f);

    float pj[10];
    #pragma unroll
    for (int j = 0; j < 10; j++) {
        float p = 0.f;
        #pragma unroll
        for (int k = 0; k < 16; k++)
            p = fmaf(h[k], s_w2[j * 512 + lane + 32 * k], p);
        #pragma unroll
        for (int o = 16; o > 0; o >>= 1) p += __shfl_xor_sync(0xffffffffu, p, o);
        pj[j] = p + s_b2[j];
    }

    float sa2 = 0.f;
    #pragma unroll
    for (int j = 0; j < 10; j++) sa2 += fabsf(pj[j]);
    const float d2 = 0.7f * sa2 / 10.f;
    float ms2 = 0.f, c2 = 0.f;
    #pragma unroll
    for (int j = 0; j < 10; j++) {
        const float a = fabsf(pj[j]);
        if (a > d2) { ms2 += a; c2 += 1.f; }
    }
    const float al2 = ms2 / c2;

    if (lane < 10) {
        float v = 0.f;
        #pragma unroll
        for (int j = 0; j < 10; j++) if (lane == j) v = pj[j];
        out[(size_t)s * 10 + lane] = (v > d2) ? al2 : ((v < -d2) ? -al2 : 0.f);
    }
}

// ============================================================================
extern "C" void kernel_launch(void* const* d_in, const int* in_sizes, int n_in,
                              void* d_out, int out_size)
{
    const float* x       = (const float*)d_in[0];
    const float* conv1_w = (const float*)d_in[1];
    const float* conv1_b = (const float*)d_in[2];
    const float* bn1_g   = (const float*)d_in[3];
    const float* bn1_b   = (const float*)d_in[4];
    const float* conv2_w = (const float*)d_in[5];
    const float* conv2_b = (const float*)d_in[6];
    const float* bn2_g   = (const float*)d_in[7];
    const float* bn2_b   = (const float*)d_in[8];
    const float* fc1_w   = (const float*)d_in[9];
    const float* fc1_b   = (const float*)d_in[10];
    const float* fc2_w   = (const float*)d_in[11];
    const float* fc2_b   = (const float*)d_in[12];
    float* out = (float*)d_out;

    int nsm = 148;
    cudaDeviceGetAttribute(&nsm, cudaDevAttrMultiProcessorCount, 0);
    if (nsm <= 0) nsm = 148;

    cudaFuncSetAttribute(k2_conv2, cudaFuncAttributeMaxDynamicSharedMemorySize, K2_SMEM);

    k0_pack_w2<<<100, 256>>>(conv2_w);
    k1_conv1<<<BATCH, 384>>>(x, conv1_w, conv1_b, bn1_g, bn1_b);
    k2_conv2<<<nsm, 256, K2_SMEM>>>(conv2_b, bn2_g, bn2_b);
    k3_fc1<<<dim3(8, 32), 128>>>(fc1_w, fc1_b);
    k4_fc2<<<256, 256>>>(fc2_w, fc2_b, out);
}

// round 5
// speedup vs baseline: 1.2913x; 1.0677x over previous
#include <cuda_runtime.h>
#include <math.h>

#define BATCH 2048
#define BN_INV 0.9999950000374997f   // 1/sqrt(1+1e-5)

typedef unsigned long long u64;

#define FMA2(acc, a, b) asm("fma.rn.f32x2 %0, %1, %2, %0;" : "+l"(acc) : "l"(a), "l"(b))
__device__ __forceinline__ u64 pack2(float lo, float hi) {
    u64 r; asm("mov.b64 %0, {%1, %2};" : "=l"(r) : "f"(lo), "f"(hi)); return r;
}
__device__ __forceinline__ float2 unpack2(u64 v) {
    float2 f; asm("mov.b64 {%0, %1}, %2;" : "=f"(f.x), "=f"(f.y) : "l"(v)); return f;
}
__device__ __forceinline__ float ternv(float v, float delta, float alpha) {
    return (v > delta) ? alpha : ((v < -delta) ? -alpha : 0.f);
}

// ---------------- scratch ---------------------------------------------------
__device__ float g_h1[BATCH * 32 * 12 * 12];
__device__ float g_h2[BATCH * 1024];
__device__ float g_fc1[BATCH * 512];
__device__ u64   g_w2p[25600];     // conv2 weights, paired (oc, oc+32)

// ---------------- block reductions ------------------------------------------
__device__ __forceinline__ float block_reduce(float v, float* s_red, int tid, int nthr) {
    #pragma unroll
    for (int o = 16; o > 0; o >>= 1) v += __shfl_down_sync(0xffffffffu, v, o);
    int wid = tid >> 5, lane = tid & 31, nw = nthr >> 5;
    __syncthreads();
    if (lane == 0) s_red[wid] = v;
    __syncthreads();
    if (wid == 0) {
        float x = (lane < nw) ? s_red[lane] : 0.f;
        #pragma unroll
        for (int o = 16; o > 0; o >>= 1) x += __shfl_down_sync(0xffffffffu, x, o);
        if (lane == 0) s_red[0] = x;
    }
    __syncthreads();
    return s_red[0];
}

__device__ __forceinline__ float2 block_reduce2(float a, float b, float* s_red, int tid, int nthr) {
    #pragma unroll
    for (int o = 16; o > 0; o >>= 1) {
        a += __shfl_down_sync(0xffffffffu, a, o);
        b += __shfl_down_sync(0xffffffffu, b, o);
    }
    int wid = tid >> 5, lane = tid & 31, nw = nthr >> 5;
    __syncthreads();
    if (lane == 0) { s_red[wid] = a; s_red[32 + wid] = b; }
    __syncthreads();
    if (wid == 0) {
        float x = (lane < nw) ? s_red[lane] : 0.f;
        float y = (lane < nw) ? s_red[32 + lane] : 0.f;
        #pragma unroll
        for (int o = 16; o > 0; o >>= 1) {
            x += __shfl_down_sync(0xffffffffu, x, o);
            y += __shfl_down_sync(0xffffffffu, y, o);
        }
        if (lane == 0) { s_red[0] = x; s_red[32] = y; }
    }
    __syncthreads();
    float2 r; r.x = s_red[0]; r.y = s_red[32];
    return r;
}

// ============================================================================
// K0: repack conv2 weights into pairs: g_w2p[(ic*25+pos)*32+ocl]
// ============================================================================
__global__ void k0_pack_w2(const float* __restrict__ w) {
    int i = blockIdx.x * 256 + threadIdx.x;
    if (i < 25600) {
        int icpos = i >> 5, ocl = i & 31;
        g_w2p[i] = pack2(w[ocl * 800 + icpos], w[(ocl + 32) * 800 + icpos]);
    }
}

// ============================================================================
// K1: conv1 + ternarize + BN + maxpool + relu. (proven r2 version)
// ============================================================================
__global__ __launch_bounds__(384) void k1_conv1(
    const float* __restrict__ x, const float* __restrict__ w,
    const float* __restrict__ bias, const float* __restrict__ bng,
    const float* __restrict__ bnb)
{
    __shared__ float s_in[784];
    __shared__ u64   s_w[400];
    __shared__ u64   s_b[16];
    __shared__ float s_ex[9504];
    __shared__ float s_red[64];

    const int tid = threadIdx.x;
    const int s = blockIdx.x;
    const int ocl = tid & 15;
    const int oy  = tid >> 4;

    const float* xin = x + s * 784;
    for (int i = tid; i < 784; i += 384) s_in[i] = xin[i];
    for (int i = tid; i < 400; i += 384) {
        int pos = i >> 4, oc2 = i & 15;
        s_w[i] = pack2(w[oc2 * 25 + pos], w[(oc2 + 16) * 25 + pos]);
    }
    if (tid < 16) s_b[tid] = pack2(bias[tid], bias[tid + 16]);
    __syncthreads();

    u64 acc[24];
    {
        const u64 bb = s_b[ocl];
        #pragma unroll
        for (int p = 0; p < 24; p++) acc[p] = bb;
    }

    #pragma unroll
    for (int ky = 0; ky < 5; ky++) {
        const float* rp = s_in + (oy + ky) * 28;
        u64 rp2[28];
        #pragma unroll
        for (int t = 0; t < 7; t++) {
            const float4 q = *(const float4*)(rp + t * 4);
            rp2[t * 4 + 0] = pack2(q.x, q.x);
            rp2[t * 4 + 1] = pack2(q.y, q.y);
            rp2[t * 4 + 2] = pack2(q.z, q.z);
            rp2[t * 4 + 3] = pack2(q.w, q.w);
        }
        #pragma unroll
        for (int kx = 0; kx < 5; kx++) {
            const u64 wv = s_w[(ky * 5 + kx) * 16 + ocl];
            #pragma unroll
            for (int p = 0; p < 24; p++) FMA2(acc[p], rp2[p + kx], wv);
        }
    }

    float sa = 0.f;
    #pragma unroll
    for (int p = 0; p < 24; p++) {
        const float2 t = unpack2(acc[p]);
        sa += fabsf(t.x) + fabsf(t.y);
    }
    const float tot = block_reduce(sa, s_red, tid, 384);
    const float delta = 0.7f * tot / 18432.f;

    float ms = 0.f, ct = 0.f;
    #pragma unroll
    for (int p = 0; p < 24; p++) {
        const float2 t = unpack2(acc[p]);
        float a = fabsf(t.x); if (a > delta) { ms += a; ct += 1.f; }
        a = fabsf(t.y);       if (a > delta) { ms += a; ct += 1.f; }
    }
    const float2 mc = block_reduce2(ms, ct, s_red, tid, 384);
    const float alpha = mc.x / mc.y;

    const float g0 = bng[ocl] * BN_INV, b0 = bnb[ocl];
    const float g1 = bng[ocl + 16] * BN_INV, b1 = bnb[ocl + 16];

    #pragma unroll
    for (int p = 0; p < 12; p++) {
        const float2 ta = unpack2(acc[2 * p]);
        const float2 tb = unpack2(acc[2 * p + 1]);
        const float mlo = fmaxf(fmaf(ternv(ta.x, delta, alpha), g0, b0),
                                fmaf(ternv(tb.x, delta, alpha), g0, b0));
        const float mhi = fmaxf(fmaf(ternv(ta.y, delta, alpha), g1, b1),
                                fmaf(ternv(tb.y, delta, alpha), g1, b1));
        s_ex[(oy * 12 + p) * 33 + ocl]      = mlo;
        s_ex[(oy * 12 + p) * 33 + ocl + 16] = mhi;
    }
    __syncthreads();

    for (int i = tid; i < 4608; i += 384) {
        const int oc = i / 144, r = i % 144, py = r / 12, px = r % 12;
        const float m = fmaxf(s_ex[((2 * py) * 12 + px) * 33 + oc],
                              s_ex[((2 * py + 1) * 12 + px) * 33 + oc]);
        g_h1[s * 4608 + i] = fmaxf(m, 0.f);
    }
}

// ============================================================================
// K2: conv2 fused. PERSISTENT, 256 threads, input prefetch pipeline.
// smem: s_w 204800 | s_in 18432 | s_ex 8320 | s_red 192  = 231744 B
// ============================================================================
#define K2_SMEM (25600 * 8 + 4608 * 4 + 2080 * 4 + 48 * 4)

__global__ __launch_bounds__(256) void k2_conv2(
    const float* __restrict__ bias, const float* __restrict__ bng,
    const float* __restrict__ bnb)
{
    extern __shared__ char smraw[];
    u64*   s_w    = (u64*)smraw;                               // 25600 pairs
    float* s_in   = (float*)(smraw + 25600 * 8);               // 4608
    float* s_ex   = s_in + 4608;                               // [32][65]
    float* s_redA = s_ex + 2080;
    float* s_redB = s_redA + 16;
    float* s_redC = s_redB + 16;

    const int tid = threadIdx.x;
    const int lane = tid & 31, wid = tid >> 5;
    const int ocl = tid & 31;
    const int oy  = tid >> 5;        // 0..7, warp-uniform

    for (int i = tid; i < 25600; i += 256) s_w[i] = g_w2p[i];

    const u64 bb = pack2(bias[ocl], bias[ocl + 32]);
    const float g0 = bng[ocl] * BN_INV, b0 = bnb[ocl];
    const float g1 = bng[ocl + 32] * BN_INV, b1 = bnb[ocl + 32];

    // prologue: load first sample
    {
        const float4* hin = (const float4*)(g_h1 + blockIdx.x * 4608);
        float4* si4 = (float4*)s_in;
        for (int i = tid; i < 1152; i += 256) si4[i] = hin[i];
    }
    __syncthreads();

    for (int s = blockIdx.x; s < BATCH; s += gridDim.x) {
        // prefetch next sample into registers (consumed after sync A)
        const int sn = s + gridDim.x;
        const bool hn = sn < BATCH;
        float4 pf0, pf1, pf2, pf3, pf4;
        if (hn) {
            const float4* nin = (const float4*)(g_h1 + (size_t)sn * 4608);
            pf0 = nin[tid];       pf1 = nin[tid + 256];
            pf2 = nin[tid + 512]; pf3 = nin[tid + 768];
            if (tid < 128) pf4 = nin[tid + 1024];
        }

        u64 acc[8];
        #pragma unroll
        for (int j = 0; j < 8; j++) acc[j] = bb;

        for (int ic = 0; ic < 32; ic++) {
            #pragma unroll
            for (int ky = 0; ky < 5; ky++) {
                const float* rp = s_in + ic * 144 + (oy + ky) * 12;
                const float4 q0 = *(const float4*)(rp);
                const float4 q1 = *(const float4*)(rp + 4);
                const float4 q2 = *(const float4*)(rp + 8);
                u64 rw[12];
                rw[0]  = pack2(q0.x, q0.x); rw[1]  = pack2(q0.y, q0.y);
                rw[2]  = pack2(q0.z, q0.z); rw[3]  = pack2(q0.w, q0.w);
                rw[4]  = pack2(q1.x, q1.x); rw[5]  = pack2(q1.y, q1.y);
                rw[6]  = pack2(q1.z, q1.z); rw[7]  = pack2(q1.w, q1.w);
                rw[8]  = pack2(q2.x, q2.x); rw[9]  = pack2(q2.y, q2.y);
                rw[10] = pack2(q2.z, q2.z); rw[11] = pack2(q2.w, q2.w);
                const u64* wrow = s_w + (ic * 25 + ky * 5) * 32 + ocl;
                #pragma unroll
                for (int kx = 0; kx < 5; kx++) {
                    const u64 wv = wrow[kx * 32];
                    #pragma unroll
                    for (int j = 0; j < 8; j++) FMA2(acc[j], rw[j + kx], wv);
                }
            }
        }

        // stats pass 1
        float sa = 0.f;
        #pragma unroll
        for (int j = 0; j < 8; j++) {
            const float2 t = unpack2(acc[j]);
            sa += fabsf(t.x) + fabsf(t.y);
        }
        #pragma unroll
        for (int o = 16; o > 0; o >>= 1) sa += __shfl_down_sync(0xffffffffu, sa, o);
        if (lane == 0) s_redA[wid] = sa;
        __syncthreads();   // (A) conv reads of s_in done

        // store next sample's input
        if (hn) {
            float4* si4 = (float4*)s_in;
            si4[tid] = pf0;       si4[tid + 256] = pf1;
            si4[tid + 512] = pf2; si4[tid + 768] = pf3;
            if (tid < 128) si4[tid + 1024] = pf4;
        }

        float tot = 0.f;
        #pragma unroll
        for (int wk = 0; wk < 8; wk++) tot += s_redA[wk];
        const float delta = 0.7f * tot / 4096.f;

        float ms = 0.f, ct = 0.f;
        #pragma unroll
        for (int j = 0; j < 8; j++) {
            const float2 t = unpack2(acc[j]);
            float a = fabsf(t.x); if (a > delta) { ms += a; ct += 1.f; }
            a = fabsf(t.y);       if (a > delta) { ms += a; ct += 1.f; }
        }
        #pragma unroll
        for (int o = 16; o > 0; o >>= 1) {
            ms += __shfl_down_sync(0xffffffffu, ms, o);
            ct += __shfl_down_sync(0xffffffffu, ct, o);
        }
        if (lane == 0) { s_redB[wid] = ms; s_redC[wid] = ct; }
        __syncthreads();   // (B)
        float mtot = 0.f, ctot = 0.f;
        #pragma unroll
        for (int wk = 0; wk < 8; wk++) { mtot += s_redB[wk]; ctot += s_redC[wk]; }
        const float alpha = mtot / ctot;

        // ternarize + BN + pool-x -> s_ex
        #pragma unroll
        for (int p = 0; p < 4; p++) {
            const float2 ta = unpack2(acc[2 * p]);
            const float2 tb = unpack2(acc[2 * p + 1]);
            const float mlo = fmaxf(fmaf(ternv(ta.x, delta, alpha), g0, b0),
                                    fmaf(ternv(tb.x, delta, alpha), g0, b0));
            const float mhi = fmaxf(fmaf(ternv(ta.y, delta, alpha), g1, b1),
                                    fmaf(ternv(tb.y, delta, alpha), g1, b1));
            s_ex[(oy * 4 + p) * 65 + ocl]      = mlo;
            s_ex[(oy * 4 + p) * 65 + ocl + 32] = mhi;
        }
        __syncthreads();   // (C)

        // pool-y + relu -> g_h2 [s][1024]
        for (int i = tid; i < 1024; i += 256) {
            const int oc = i >> 4, r = i & 15, py = r >> 2, px = r & 3;
            const float m = fmaxf(s_ex[((2 * py) * 4 + px) * 65 + oc],
                                  s_ex[((2 * py + 1) * 4 + px) * 65 + oc]);
            g_h2[s * 1024 + i] = fmaxf(m, 0.f);
        }
    }
}

// ============================================================================
// K3: fc1 GEMM. 64x64 tile, 256 threads, 4m x 4n, double-buffered,
// register prefetch, ONE sync per k-tile.
// ============================================================================
__global__ __launch_bounds__(256) void k3_fc1(
    const float* __restrict__ Wf, const float* __restrict__ bf)
{
    __shared__ float As[2][16][68];
    __shared__ float Bs[2][16][68];

    const int tid = threadIdx.x;
    const int tn = tid & 15;       // n = tn*4
    const int tm = tid >> 4;       // m = tm*4
    const int bn = blockIdx.x, bm = blockIdx.y;

    const float* Ap = g_h2 + (size_t)(bm * 64) * 1024;
    const float* Bp = Wf   + (size_t)(bn * 64) * 1024;

    const int lr = tid >> 2;            // row 0..63
    const int lk = (tid & 3) * 4;       // k 0,4,8,12

    u64 acc[4][2];
    #pragma unroll
    for (int i = 0; i < 4; i++) { acc[i][0] = 0ull; acc[i][1] = 0ull; }

    // prologue: tile 0
    {
        const float4 a = *(const float4*)(Ap + lr * 1024 + lk);
        const float4 b = *(const float4*)(Bp + lr * 1024 + lk);
        As[0][lk + 0][lr] = a.x; As[0][lk + 1][lr] = a.y;
        As[0][lk + 2][lr] = a.z; As[0][lk + 3][lr] = a.w;
        Bs[0][lk + 0][lr] = b.x; Bs[0][lk + 1][lr] = b.y;
        Bs[0][lk + 2][lr] = b.z; Bs[0][lk + 3][lr] = b.w;
    }
    __syncthreads();

    for (int t = 0; t < 64; t++) {
        const int cur = t & 1;
        float4 an, bn4;
        if (t < 63) {
            an  = *(const float4*)(Ap + lr * 1024 + (t + 1) * 16 + lk);
            bn4 = *(const float4*)(Bp + lr * 1024 + (t + 1) * 16 + lk);
        }
        #pragma unroll
        for (int kk = 0; kk < 16; kk++) {
            const float4 av = *(const float4*)(&As[cur][kk][tm * 4]);
            const float4 bv = *(const float4*)(&Bs[cur][kk][tn * 4]);
            const u64 bp0 = pack2(bv.x, bv.y);
            const u64 bp1 = pack2(bv.z, bv.w);
            const u64 a0 = pack2(av.x, av.x);
            const u64 a1 = pack2(av.y, av.y);
            const u64 a2 = pack2(av.z, av.z);
            const u64 a3 = pack2(av.w, av.w);
            FMA2(acc[0][0], a0, bp0); FMA2(acc[0][1], a0, bp1);
            FMA2(acc[1][0], a1, bp0); FMA2(acc[1][1], a1, bp1);
            FMA2(acc[2][0], a2, bp0); FMA2(acc[2][1], a2, bp1);
            FMA2(acc[3][0], a3, bp0); FMA2(acc[3][1], a3, bp1);
        }
        if (t < 63) {
            const int nxt = cur ^ 1;
            As[nxt][lk + 0][lr] = an.x; As[nxt][lk + 1][lr] = an.y;
            As[nxt][lk + 2][lr] = an.z; As[nxt][lk + 3][lr] = an.w;
            Bs[nxt][lk + 0][lr] = bn4.x; Bs[nxt][lk + 1][lr] = bn4.y;
            Bs[nxt][lk + 2][lr] = bn4.z; Bs[nxt][lk + 3][lr] = bn4.w;
        }
        __syncthreads();
    }

    const int n0 = bn * 64 + tn * 4;
    const float4 bia = *(const float4*)(bf + n0);
    #pragma unroll
    for (int i = 0; i < 4; i++) {
        const int m = bm * 64 + tm * 4 + i;
        const float2 r0 = unpack2(acc[i][0]);
        const float2 r1 = unpack2(acc[i][1]);
        float4 o;
        o.x = r0.x + bia.x; o.y = r0.y + bia.y;
        o.z = r1.x + bia.z; o.w = r1.y + bia.w;
        *(float4*)(g_fc1 + (size_t)m * 512 + n0) = o;
    }
}

// ============================================================================
// K4: ternarize(512)+relu + fc2 + ternarize(10). 1 warp/sample. (proven)
// ============================================================================
__global__ __launch_bounds__(256) void k4_fc2(
    const float* __restrict__ W2, const float* __restrict__ b2,
    float* __restrict__ out)
{
    __shared__ float s_w2[5120];
    __shared__ float s_b2[10];

    const int tid = threadIdx.x;
    for (int i = tid; i < 5120; i += 256) s_w2[i] = W2[i];
    if (tid < 10) s_b2[tid] = b2[tid];
    __syncthreads();

    const int lane = tid & 31, warp = tid >> 5;
    const int s = blockIdx.x * 8 + warp;
    const float* hr = g_fc1 + (size_t)s * 512;

    float h[16];
    #pragma unroll
    for (int k = 0; k < 16; k++) h[k] = hr[lane + 32 * k];

    float sa = 0.f;
    #pragma unroll
    for (int k = 0; k < 16; k++) sa += fabsf(h[k]);
    #pragma unroll
    for (int o = 16; o > 0; o >>= 1) sa += __shfl_xor_sync(0xffffffffu, sa, o);
    const float delta = 0.7f * sa / 512.f;

    float ms = 0.f, ct = 0.f;
    #pragma unroll
    for (int k = 0; k < 16; k++) {
        const float a = fabsf(h[k]);
        if (a > delta) { ms += a; ct += 1.f; }
    }
    #pragma unroll
    for (int o = 16; o > 0; o >>= 1) {
        ms += __shfl_xor_sync(0xffffffffu, ms, o);
        ct += __shfl_xor_sync(0xffffffffu, ct, o);
    }
    const float alpha = ms / ct;

    #pragma unroll
    for (int k = 0; k < 16; k++) h[k] = fmaxf(ternv(h[k], delta, alpha), 0.f);

    float pj[10];
    #pragma unroll
    for (int j = 0; j < 10; j++) {
        float p = 0.f;
        #pragma unroll
        for (int k = 0; k < 16; k++)
            p = fmaf(h[k], s_w2[j * 512 + lane + 32 * k], p);
        #pragma unroll
        for (int o = 16; o > 0; o >>= 1) p += __shfl_xor_sync(0xffffffffu, p, o);
        pj[j] = p + s_b2[j];
    }

    float sa2 = 0.f;
    #pragma unroll
    for (int j = 0; j < 10; j++) sa2 += fabsf(pj[j]);
    const float d2 = 0.7f * sa2 / 10.f;
    float ms2 = 0.f, c2 = 0.f;
    #pragma unroll
    for (int j = 0; j < 10; j++) {
        const float a = fabsf(pj[j]);
        if (a > d2) { ms2 += a; c2 += 1.f; }
    }
    const float al2 = ms2 / c2;

    if (lane < 10) {
        float v = 0.f;
        #pragma unroll
        for (int j = 0; j < 10; j++) if (lane == j) v = pj[j];
        out[(size_t)s * 10 + lane] = (v > d2) ? al2 : ((v < -d2) ? -al2 : 0.f);
    }
}

// ============================================================================
extern "C" void kernel_launch(void* const* d_in, const int* in_sizes, int n_in,
                              void* d_out, int out_size)
{
    const float* x       = (const float*)d_in[0];
    const float* conv1_w = (const float*)d_in[1];
    const float* conv1_b = (const float*)d_in[2];
    const float* bn1_g   = (const float*)d_in[3];
    const float* bn1_b   = (const float*)d_in[4];
    const float* conv2_w = (const float*)d_in[5];
    const float* conv2_b = (const float*)d_in[6];
    const float* bn2_g   = (const float*)d_in[7];
    const float* bn2_b   = (const float*)d_in[8];
    const float* fc1_w   = (const float*)d_in[9];
    const float* fc1_b   = (const float*)d_in[10];
    const float* fc2_w   = (const float*)d_in[11];
    const float* fc2_b   = (const float*)d_in[12];
    float* out = (float*)d_out;

    int nsm = 148;
    cudaDeviceGetAttribute(&nsm, cudaDevAttrMultiProcessorCount, 0);
    if (nsm <= 0) nsm = 148;

    cudaFuncSetAttribute(k2_conv2, cudaFuncAttributeMaxDynamicSharedMemorySize, K2_SMEM);

    k0_pack_w2<<<100, 256>>>(conv2_w);
    k1_conv1<<<BATCH, 384>>>(x, conv1_w, conv1_b, bn1_g, bn1_b);
    k2_conv2<<<nsm, 256, K2_SMEM>>>(conv2_b, bn2_g, bn2_b);
    k3_fc1<<<dim3(8, 32), 256>>>(fc1_w, fc1_b);
    k4_fc2<<<256, 256>>>(fc2_w, fc2_b, out);
}

// round 6
// speedup vs baseline: 1.3171x; 1.0200x over previous
#include <cuda_runtime.h>
#include <math.h>

#define BATCH 2048
#define BN_INV 0.9999950000374997f   // 1/sqrt(1+1e-5)

typedef unsigned long long u64;

#define FMA2(acc, a, b) asm("fma.rn.f32x2 %0, %1, %2, %0;" : "+l"(acc) : "l"(a), "l"(b))
__device__ __forceinline__ u64 pack2(float lo, float hi) {
    u64 r; asm("mov.b64 %0, {%1, %2};" : "=l"(r) : "f"(lo), "f"(hi)); return r;
}
__device__ __forceinline__ float2 unpack2(u64 v) {
    float2 f; asm("mov.b64 {%0, %1}, %2;" : "=f"(f.x), "=f"(f.y) : "l"(v)); return f;
}
__device__ __forceinline__ float ternv(float v, float delta, float alpha) {
    return (v > delta) ? alpha : ((v < -delta) ? -alpha : 0.f);
}

// ---------------- scratch ---------------------------------------------------
__device__ float g_h1[BATCH * 32 * 12 * 12];
__device__ float g_h2[BATCH * 1024];
__device__ float g_fc1[BATCH * 512];
__device__ u64   g_w2p[25600];     // conv2 weights, paired (oc, oc+32)

// ---------------- block reductions ------------------------------------------
__device__ __forceinline__ float block_reduce(float v, float* s_red, int tid, int nthr) {
    #pragma unroll
    for (int o = 16; o > 0; o >>= 1) v += __shfl_down_sync(0xffffffffu, v, o);
    int wid = tid >> 5, lane = tid & 31, nw = nthr >> 5;
    __syncthreads();
    if (lane == 0) s_red[wid] = v;
    __syncthreads();
    if (wid == 0) {
        float x = (lane < nw) ? s_red[lane] : 0.f;
        #pragma unroll
        for (int o = 16; o > 0; o >>= 1) x += __shfl_down_sync(0xffffffffu, x, o);
        if (lane == 0) s_red[0] = x;
    }
    __syncthreads();
    return s_red[0];
}

__device__ __forceinline__ float2 block_reduce2(float a, float b, float* s_red, int tid, int nthr) {
    #pragma unroll
    for (int o = 16; o > 0; o >>= 1) {
        a += __shfl_down_sync(0xffffffffu, a, o);
        b += __shfl_down_sync(0xffffffffu, b, o);
    }
    int wid = tid >> 5, lane = tid & 31, nw = nthr >> 5;
    __syncthreads();
    if (lane == 0) { s_red[wid] = a; s_red[32 + wid] = b; }
    __syncthreads();
    if (wid == 0) {
        float x = (lane < nw) ? s_red[lane] : 0.f;
        float y = (lane < nw) ? s_red[32 + lane] : 0.f;
        #pragma unroll
        for (int o = 16; o > 0; o >>= 1) {
            x += __shfl_down_sync(0xffffffffu, x, o);
            y += __shfl_down_sync(0xffffffffu, y, o);
        }
        if (lane == 0) { s_red[0] = x; s_red[32] = y; }
    }
    __syncthreads();
    float2 r; r.x = s_red[0]; r.y = s_red[32];
    return r;
}

// ============================================================================
// K0: repack conv2 weights into pairs: g_w2p[(ic*25+pos)*32+ocl]
// ============================================================================
__global__ void k0_pack_w2(const float* __restrict__ w) {
    int i = blockIdx.x * 256 + threadIdx.x;
    if (i < 25600) {
        int icpos = i >> 5, ocl = i & 31;
        g_w2p[i] = pack2(w[ocl * 800 + icpos], w[(ocl + 32) * 800 + icpos]);
    }
}

// ============================================================================
// K1: conv1 + ternarize + BN + maxpool + relu. (proven)
// ============================================================================
__global__ __launch_bounds__(384) void k1_conv1(
    const float* __restrict__ x, const float* __restrict__ w,
    const float* __restrict__ bias, const float* __restrict__ bng,
    const float* __restrict__ bnb)
{
    __shared__ float s_in[784];
    __shared__ u64   s_w[400];
    __shared__ u64   s_b[16];
    __shared__ float s_ex[9504];
    __shared__ float s_red[64];

    const int tid = threadIdx.x;
    const int s = blockIdx.x;
    const int ocl = tid & 15;
    const int oy  = tid >> 4;

    const float* xin = x + s * 784;
    for (int i = tid; i < 784; i += 384) s_in[i] = xin[i];
    for (int i = tid; i < 400; i += 384) {
        int pos = i >> 4, oc2 = i & 15;
        s_w[i] = pack2(w[oc2 * 25 + pos], w[(oc2 + 16) * 25 + pos]);
    }
    if (tid < 16) s_b[tid] = pack2(bias[tid], bias[tid + 16]);
    __syncthreads();

    u64 acc[24];
    {
        const u64 bb = s_b[ocl];
        #pragma unroll
        for (int p = 0; p < 24; p++) acc[p] = bb;
    }

    #pragma unroll
    for (int ky = 0; ky < 5; ky++) {
        const float* rp = s_in + (oy + ky) * 28;
        u64 rp2[28];
        #pragma unroll
        for (int t = 0; t < 7; t++) {
            const float4 q = *(const float4*)(rp + t * 4);
            rp2[t * 4 + 0] = pack2(q.x, q.x);
            rp2[t * 4 + 1] = pack2(q.y, q.y);
            rp2[t * 4 + 2] = pack2(q.z, q.z);
            rp2[t * 4 + 3] = pack2(q.w, q.w);
        }
        #pragma unroll
        for (int kx = 0; kx < 5; kx++) {
            const u64 wv = s_w[(ky * 5 + kx) * 16 + ocl];
            #pragma unroll
            for (int p = 0; p < 24; p++) FMA2(acc[p], rp2[p + kx], wv);
        }
    }

    float sa = 0.f;
    #pragma unroll
    for (int p = 0; p < 24; p++) {
        const float2 t = unpack2(acc[p]);
        sa += fabsf(t.x) + fabsf(t.y);
    }
    const float tot = block_reduce(sa, s_red, tid, 384);
    const float delta = 0.7f * tot / 18432.f;

    float ms = 0.f, ct = 0.f;
    #pragma unroll
    for (int p = 0; p < 24; p++) {
        const float2 t = unpack2(acc[p]);
        float a = fabsf(t.x); if (a > delta) { ms += a; ct += 1.f; }
        a = fabsf(t.y);       if (a > delta) { ms += a; ct += 1.f; }
    }
    const float2 mc = block_reduce2(ms, ct, s_red, tid, 384);
    const float alpha = mc.x / mc.y;

    const float g0 = bng[ocl] * BN_INV, b0 = bnb[ocl];
    const float g1 = bng[ocl + 16] * BN_INV, b1 = bnb[ocl + 16];

    #pragma unroll
    for (int p = 0; p < 12; p++) {
        const float2 ta = unpack2(acc[2 * p]);
        const float2 tb = unpack2(acc[2 * p + 1]);
        const float mlo = fmaxf(fmaf(ternv(ta.x, delta, alpha), g0, b0),
                                fmaf(ternv(tb.x, delta, alpha), g0, b0));
        const float mhi = fmaxf(fmaf(ternv(ta.y, delta, alpha), g1, b1),
                                fmaf(ternv(tb.y, delta, alpha), g1, b1));
        s_ex[(oy * 12 + p) * 33 + ocl]      = mlo;
        s_ex[(oy * 12 + p) * 33 + ocl + 16] = mhi;
    }
    __syncthreads();

    for (int i = tid; i < 4608; i += 384) {
        const int oc = i / 144, r = i % 144, py = r / 12, px = r % 12;
        const float m = fmaxf(s_ex[((2 * py) * 12 + px) * 33 + oc],
                              s_ex[((2 * py + 1) * 12 + px) * 33 + oc]);
        g_h1[s * 4608 + i] = fmaxf(m, 0.f);
    }
}

// ============================================================================
// K2: conv2 fused. PERSISTENT, 256 threads, input prefetch pipeline. (proven r5)
// ============================================================================
#define K2_SMEM (25600 * 8 + 4608 * 4 + 2080 * 4 + 48 * 4)

__global__ __launch_bounds__(256) void k2_conv2(
    const float* __restrict__ bias, const float* __restrict__ bng,
    const float* __restrict__ bnb)
{
    extern __shared__ char smraw[];
    u64*   s_w    = (u64*)smraw;
    float* s_in   = (float*)(smraw + 25600 * 8);
    float* s_ex   = s_in + 4608;
    float* s_redA = s_ex + 2080;
    float* s_redB = s_redA + 16;
    float* s_redC = s_redB + 16;

    const int tid = threadIdx.x;
    const int lane = tid & 31, wid = tid >> 5;
    const int ocl = tid & 31;
    const int oy  = tid >> 5;

    for (int i = tid; i < 25600; i += 256) s_w[i] = g_w2p[i];

    const u64 bb = pack2(bias[ocl], bias[ocl + 32]);
    const float g0 = bng[ocl] * BN_INV, b0 = bnb[ocl];
    const float g1 = bng[ocl + 32] * BN_INV, b1 = bnb[ocl + 32];

    {
        const float4* hin = (const float4*)(g_h1 + blockIdx.x * 4608);
        float4* si4 = (float4*)s_in;
        for (int i = tid; i < 1152; i += 256) si4[i] = hin[i];
    }
    __syncthreads();

    for (int s = blockIdx.x; s < BATCH; s += gridDim.x) {
        const int sn = s + gridDim.x;
        const bool hn = sn < BATCH;
        float4 pf0, pf1, pf2, pf3, pf4;
        if (hn) {
            const float4* nin = (const float4*)(g_h1 + (size_t)sn * 4608);
            pf0 = nin[tid];       pf1 = nin[tid + 256];
            pf2 = nin[tid + 512]; pf3 = nin[tid + 768];
            if (tid < 128) pf4 = nin[tid + 1024];
        }

        u64 acc[8];
        #pragma unroll
        for (int j = 0; j < 8; j++) acc[j] = bb;

        for (int ic = 0; ic < 32; ic++) {
            #pragma unroll
            for (int ky = 0; ky < 5; ky++) {
                const float* rp = s_in + ic * 144 + (oy + ky) * 12;
                const float4 q0 = *(const float4*)(rp);
                const float4 q1 = *(const float4*)(rp + 4);
                const float4 q2 = *(const float4*)(rp + 8);
                u64 rw[12];
                rw[0]  = pack2(q0.x, q0.x); rw[1]  = pack2(q0.y, q0.y);
                rw[2]  = pack2(q0.z, q0.z); rw[3]  = pack2(q0.w, q0.w);
                rw[4]  = pack2(q1.x, q1.x); rw[5]  = pack2(q1.y, q1.y);
                rw[6]  = pack2(q1.z, q1.z); rw[7]  = pack2(q1.w, q1.w);
                rw[8]  = pack2(q2.x, q2.x); rw[9]  = pack2(q2.y, q2.y);
                rw[10] = pack2(q2.z, q2.z); rw[11] = pack2(q2.w, q2.w);
                const u64* wrow = s_w + (ic * 25 + ky * 5) * 32 + ocl;
                #pragma unroll
                for (int kx = 0; kx < 5; kx++) {
                    const u64 wv = wrow[kx * 32];
                    #pragma unroll
                    for (int j = 0; j < 8; j++) FMA2(acc[j], rw[j + kx], wv);
                }
            }
        }

        float sa = 0.f;
        #pragma unroll
        for (int j = 0; j < 8; j++) {
            const float2 t = unpack2(acc[j]);
            sa += fabsf(t.x) + fabsf(t.y);
        }
        #pragma unroll
        for (int o = 16; o > 0; o >>= 1) sa += __shfl_down_sync(0xffffffffu, sa, o);
        if (lane == 0) s_redA[wid] = sa;
        __syncthreads();   // (A)

        if (hn) {
            float4* si4 = (float4*)s_in;
            si4[tid] = pf0;       si4[tid + 256] = pf1;
            si4[tid + 512] = pf2; si4[tid + 768] = pf3;
            if (tid < 128) si4[tid + 1024] = pf4;
        }

        float tot = 0.f;
        #pragma unroll
        for (int wk = 0; wk < 8; wk++) tot += s_redA[wk];
        const float delta = 0.7f * tot / 4096.f;

        float ms = 0.f, ct = 0.f;
        #pragma unroll
        for (int j = 0; j < 8; j++) {
            const float2 t = unpack2(acc[j]);
            float a = fabsf(t.x); if (a > delta) { ms += a; ct += 1.f; }
            a = fabsf(t.y);       if (a > delta) { ms += a; ct += 1.f; }
        }
        #pragma unroll
        for (int o = 16; o > 0; o >>= 1) {
            ms += __shfl_down_sync(0xffffffffu, ms, o);
            ct += __shfl_down_sync(0xffffffffu, ct, o);
        }
        if (lane == 0) { s_redB[wid] = ms; s_redC[wid] = ct; }
        __syncthreads();   // (B)
        float mtot = 0.f, ctot = 0.f;
        #pragma unroll
        for (int wk = 0; wk < 8; wk++) { mtot += s_redB[wk]; ctot += s_redC[wk]; }
        const float alpha = mtot / ctot;

        #pragma unroll
        for (int p = 0; p < 4; p++) {
            const float2 ta = unpack2(acc[2 * p]);
            const float2 tb = unpack2(acc[2 * p + 1]);
            const float mlo = fmaxf(fmaf(ternv(ta.x, delta, alpha), g0, b0),
                                    fmaf(ternv(tb.x, delta, alpha), g0, b0));
            const float mhi = fmaxf(fmaf(ternv(ta.y, delta, alpha), g1, b1),
                                    fmaf(ternv(tb.y, delta, alpha), g1, b1));
            s_ex[(oy * 4 + p) * 65 + ocl]      = mlo;
            s_ex[(oy * 4 + p) * 65 + ocl + 32] = mhi;
        }
        __syncthreads();   // (C)

        for (int i = tid; i < 1024; i += 256) {
            const int oc = i >> 4, r = i & 15, py = r >> 2, px = r & 3;
            const float m = fmaxf(s_ex[((2 * py) * 4 + px) * 65 + oc],
                                  s_ex[((2 * py + 1) * 4 + px) * 65 + oc]);
            g_h2[s * 1024 + i] = fmaxf(m, 0.f);
        }
    }
}

// ============================================================================
// K3: fc1 GEMM. 128x64 tile, 256 threads, 8m x 4n microtile, acc paired
// over m (A side = contiguous u64 from smem, zero A-pack MOVs).
// Double-buffered, reg-prefetch, one sync/tile. Grid 8x16 = 128 CTAs (1 wave).
// ============================================================================
__global__ __launch_bounds__(256) void k3_fc1(
    const float* __restrict__ Wf, const float* __restrict__ bf)
{
    __shared__ float As[2][16][132];   // [k][m], stride 132 (16B aligned rows)
    __shared__ float Bs[2][16][68];    // [k][n]

    const int tid = threadIdx.x;
    const int tn = tid & 15;       // n = tn*4
    const int tm = tid >> 4;       // m = tm*8 (0..15)
    const int bn = blockIdx.x;     // 0..7
    const int bm = blockIdx.y;     // 0..15

    const float* Ap = g_h2 + (size_t)(bm * 128) * 1024;
    const float* Bp = Wf   + (size_t)(bn * 64) * 1024;

    const int lrA = tid >> 1;           // A row 0..127
    const int lkA = (tid & 1) * 8;      // k 0 or 8
    const int lrB = tid >> 2;           // B row 0..63
    const int lkB = (tid & 3) * 4;      // k 0,4,8,12

    u64 acc[4][4];   // [m-pair][n]
    #pragma unroll
    for (int i = 0; i < 4; i++)
        #pragma unroll
        for (int j = 0; j < 4; j++) acc[i][j] = 0ull;

    // prologue: tile 0
    {
        const float4 a0 = *(const float4*)(Ap + lrA * 1024 + lkA);
        const float4 a1 = *(const float4*)(Ap + lrA * 1024 + lkA + 4);
        const float4 b  = *(const float4*)(Bp + lrB * 1024 + lkB);
        As[0][lkA + 0][lrA] = a0.x; As[0][lkA + 1][lrA] = a0.y;
        As[0][lkA + 2][lrA] = a0.z; As[0][lkA + 3][lrA] = a0.w;
        As[0][lkA + 4][lrA] = a1.x; As[0][lkA + 5][lrA] = a1.y;
        As[0][lkA + 6][lrA] = a1.z; As[0][lkA + 7][lrA] = a1.w;
        Bs[0][lkB + 0][lrB] = b.x; Bs[0][lkB + 1][lrB] = b.y;
        Bs[0][lkB + 2][lrB] = b.z; Bs[0][lkB + 3][lrB] = b.w;
    }
    __syncthreads();

    for (int t = 0; t < 64; t++) {
        const int cur = t & 1;
        float4 an0, an1, bn4;
        if (t < 63) {
            an0 = *(const float4*)(Ap + lrA * 1024 + (t + 1) * 16 + lkA);
            an1 = *(const float4*)(Ap + lrA * 1024 + (t + 1) * 16 + lkA + 4);
            bn4 = *(const float4*)(Bp + lrB * 1024 + (t + 1) * 16 + lkB);
        }
        #pragma unroll
        for (int kk = 0; kk < 16; kk++) {
            const ulonglong2 am01 = *(const ulonglong2*)&As[cur][kk][tm * 8];
            const ulonglong2 am23 = *(const ulonglong2*)&As[cur][kk][tm * 8 + 4];
            const float4 bv = *(const float4*)&Bs[cur][kk][tn * 4];
            const u64 b0 = pack2(bv.x, bv.x);
            const u64 b1 = pack2(bv.y, bv.y);
            const u64 b2 = pack2(bv.z, bv.z);
            const u64 b3 = pack2(bv.w, bv.w);
            FMA2(acc[0][0], am01.x, b0); FMA2(acc[0][1], am01.x, b1);
            FMA2(acc[0][2], am01.x, b2); FMA2(acc[0][3], am01.x, b3);
            FMA2(acc[1][0], am01.y, b0); FMA2(acc[1][1], am01.y, b1);
            FMA2(acc[1][2], am01.y, b2); FMA2(acc[1][3], am01.y, b3);
            FMA2(acc[2][0], am23.x, b0); FMA2(acc[2][1], am23.x, b1);
            FMA2(acc[2][2], am23.x, b2); FMA2(acc[2][3], am23.x, b3);
            FMA2(acc[3][0], am23.y, b0); FMA2(acc[3][1], am23.y, b1);
            FMA2(acc[3][2], am23.y, b2); FMA2(acc[3][3], am23.y, b3);
        }
        if (t < 63) {
            const int nxt = cur ^ 1;
            As[nxt][lkA + 0][lrA] = an0.x; As[nxt][lkA + 1][lrA] = an0.y;
            As[nxt][lkA + 2][lrA] = an0.z; As[nxt][lkA + 3][lrA] = an0.w;
            As[nxt][lkA + 4][lrA] = an1.x; As[nxt][lkA + 5][lrA] = an1.y;
            As[nxt][lkA + 6][lrA] = an1.z; As[nxt][lkA + 7][lrA] = an1.w;
            Bs[nxt][lkB + 0][lrB] = bn4.x; Bs[nxt][lkB + 1][lrB] = bn4.y;
            Bs[nxt][lkB + 2][lrB] = bn4.z; Bs[nxt][lkB + 3][lrB] = bn4.w;
        }
        __syncthreads();
    }

    const int n0 = bn * 64 + tn * 4;
    const float4 bia = *(const float4*)(bf + n0);
    #pragma unroll
    for (int i = 0; i < 4; i++) {
        const float2 r0 = unpack2(acc[i][0]);
        const float2 r1 = unpack2(acc[i][1]);
        const float2 r2 = unpack2(acc[i][2]);
        const float2 r3 = unpack2(acc[i][3]);
        const int m = bm * 128 + tm * 8 + 2 * i;
        float4 oe, oo;
        oe.x = r0.x + bia.x; oe.y = r1.x + bia.y;
        oe.z = r2.x + bia.z; oe.w = r3.x + bia.w;
        oo.x = r0.y + bia.x; oo.y = r1.y + bia.y;
        oo.z = r2.y + bia.z; oo.w = r3.y + bia.w;
        *(float4*)(g_fc1 + (size_t)m * 512 + n0)       = oe;
        *(float4*)(g_fc1 + (size_t)(m + 1) * 512 + n0) = oo;
    }
}

// ============================================================================
// K4: ternarize(512)+relu + fc2 + ternarize(10). 1 warp/sample. (proven)
// ============================================================================
__global__ __launch_bounds__(256) void k4_fc2(
    const float* __restrict__ W2, const float* __restrict__ b2,
    float* __restrict__ out)
{
    __shared__ float s_w2[5120];
    __shared__ float s_b2[10];

    const int tid = threadIdx.x;
    for (int i = tid; i < 5120; i += 256) s_w2[i] = W2[i];
    if (tid < 10) s_b2[tid] = b2[tid];
    __syncthreads();

    const int lane = tid & 31, warp = tid >> 5;
    const int s = blockIdx.x * 8 + warp;
    const float* hr = g_fc1 + (size_t)s * 512;

    float h[16];
    #pragma unroll
    for (int k = 0; k < 16; k++) h[k] = hr[lane + 32 * k];

    float sa = 0.f;
    #pragma unroll
    for (int k = 0; k < 16; k++) sa += fabsf(h[k]);
    #pragma unroll
    for (int o = 16; o > 0; o >>= 1) sa += __shfl_xor_sync(0xffffffffu, sa, o);
    const float delta = 0.7f * sa / 512.f;

    float ms = 0.f, ct = 0.f;
    #pragma unroll
    for (int k = 0; k < 16; k++) {
        const float a = fabsf(h[k]);
        if (a > delta) { ms += a; ct += 1.f; }
    }
    #pragma unroll
    for (int o = 16; o > 0; o >>= 1) {
        ms += __shfl_xor_sync(0xffffffffu, ms, o);
        ct += __shfl_xor_sync(0xffffffffu, ct, o);
    }
    const float alpha = ms / ct;

    #pragma unroll
    for (int k = 0; k < 16; k++) h[k] = fmaxf(ternv(h[k], delta, alpha), 0.f);

    float pj[10];
    #pragma unroll
    for (int j = 0; j < 10; j++) {
        float p = 0.f;
        #pragma unroll
        for (int k = 0; k < 16; k++)
            p = fmaf(h[k], s_w2[j * 512 + lane + 32 * k], p);
        #pragma unroll
        for (int o = 16; o > 0; o >>= 1) p += __shfl_xor_sync(0xffffffffu, p, o);
        pj[j] = p + s_b2[j];
    }

    float sa2 = 0.f;
    #pragma unroll
    for (int j = 0; j < 10; j++) sa2 += fabsf(pj[j]);
    const float d2 = 0.7f * sa2 / 10.f;
    float ms2 = 0.f, c2 = 0.f;
    #pragma unroll
    for (int j = 0; j < 10; j++) {
        const float a = fabsf(pj[j]);
        if (a > d2) { ms2 += a; c2 += 1.f; }
    }
    const float al2 = ms2 / c2;

    if (lane < 10) {
        float v = 0.f;
        #pragma unroll
        for (int j = 0; j < 10; j++) if (lane == j) v = pj[j];
        out[(size_t)s * 10 + lane] = (v > d2) ? al2 : ((v < -d2) ? -al2 : 0.f);
    }
}

// ============================================================================
extern "C" void kernel_launch(void* const* d_in, const int* in_sizes, int n_in,
                              void* d_out, int out_size)
{
    const float* x       = (const float*)d_in[0];
    const float* conv1_w = (const float*)d_in[1];
    const float* conv1_b = (const float*)d_in[2];
    const float* bn1_g   = (const float*)d_in[3];
    const float* bn1_b   = (const float*)d_in[4];
    const float* conv2_w = (const float*)d_in[5];
    const float* conv2_b = (const float*)d_in[6];
    const float* bn2_g   = (const float*)d_in[7];
    const float* bn2_b   = (const float*)d_in[8];
    const float* fc1_w   = (const float*)d_in[9];
    const float* fc1_b   = (const float*)d_in[10];
    const float* fc2_w   = (const float*)d_in[11];
    const float* fc2_b   = (const float*)d_in[12];
    float* out = (float*)d_out;

    int nsm = 148;
    cudaDeviceGetAttribute(&nsm, cudaDevAttrMultiProcessorCount, 0);
    if (nsm <= 0) nsm = 148;

    cudaFuncSetAttribute(k2_conv2, cudaFuncAttributeMaxDynamicSharedMemorySize, K2_SMEM);

    k0_pack_w2<<<100, 256>>>(conv2_w);
    k1_conv1<<<BATCH, 384>>>(x, conv1_w, conv1_b, bn1_g, bn1_b);
    k2_conv2<<<nsm, 256, K2_SMEM>>>(conv2_b, bn2_g, bn2_b);
    k3_fc1<<<dim3(8, 16), 256>>>(fc1_w, fc1_b);
    k4_fc2<<<256, 256>>>(fc2_w, fc2_b, out);
}

// round 8
// speedup vs baseline: 1.3263x; 1.0070x over previous
#include <cuda_runtime.h>
#include <math.h>

#define BATCH 2048
#define BN_INV 0.9999950000374997f   // 1/sqrt(1+1e-5)

typedef unsigned long long u64;

#define FMA2(acc, a, b) asm("fma.rn.f32x2 %0, %1, %2, %0;" : "+l"(acc) : "l"(a), "l"(b))
__device__ __forceinline__ u64 pack2(float lo, float hi) {
    u64 r; asm("mov.b64 %0, {%1, %2};" : "=l"(r) : "f"(lo), "f"(hi)); return r;
}
__device__ __forceinline__ float2 unpack2(u64 v) {
    float2 f; asm("mov.b64 {%0, %1}, %2;" : "=f"(f.x), "=f"(f.y) : "l"(v)); return f;
}
__device__ __forceinline__ float ternv(float v, float delta, float alpha) {
    return (v > delta) ? alpha : ((v < -delta) ? -alpha : 0.f);
}

// ---------------- scratch ---------------------------------------------------
__device__ float g_h1[BATCH * 32 * 12 * 12];
__device__ float g_h2[BATCH * 1024];
__device__ float g_fc1[BATCH * 512];
__device__ u64   g_w2p[25600];     // conv2 weights, paired (oc, oc+32)

// ---------------- block reductions ------------------------------------------
__device__ __forceinline__ float block_reduce(float v, float* s_red, int tid, int nthr) {
    #pragma unroll
    for (int o = 16; o > 0; o >>= 1) v += __shfl_down_sync(0xffffffffu, v, o);
    int wid = tid >> 5, lane = tid & 31, nw = nthr >> 5;
    __syncthreads();
    if (lane == 0) s_red[wid] = v;
    __syncthreads();
    if (wid == 0) {
        float x = (lane < nw) ? s_red[lane] : 0.f;
        #pragma unroll
        for (int o = 16; o > 0; o >>= 1) x += __shfl_down_sync(0xffffffffu, x, o);
        if (lane == 0) s_red[0] = x;
    }
    __syncthreads();
    return s_red[0];
}

__device__ __forceinline__ float2 block_reduce2(float a, float b, float* s_red, int tid, int nthr) {
    #pragma unroll
    for (int o = 16; o > 0; o >>= 1) {
        a += __shfl_down_sync(0xffffffffu, a, o);
        b += __shfl_down_sync(0xffffffffu, b, o);
    }
    int wid = tid >> 5, lane = tid & 31, nw = nthr >> 5;
    __syncthreads();
    if (lane == 0) { s_red[wid] = a; s_red[32 + wid] = b; }
    __syncthreads();
    if (wid == 0) {
        float x = (lane < nw) ? s_red[lane] : 0.f;
        float y = (lane < nw) ? s_red[32 + lane] : 0.f;
        #pragma unroll
        for (int o = 16; o > 0; o >>= 1) {
            x += __shfl_down_sync(0xffffffffu, x, o);
            y += __shfl_down_sync(0xffffffffu, y, o);
        }
        if (lane == 0) { s_red[0] = x; s_red[32] = y; }
    }
    __syncthreads();
    float2 r; r.x = s_red[0]; r.y = s_red[32];
    return r;
}

// ============================================================================
// K0: repack conv2 weights into pairs: g_w2p[(ic*25+pos)*32+ocl]
// ============================================================================
__global__ void k0_pack_w2(const float* __restrict__ w) {
    int i = blockIdx.x * 256 + threadIdx.x;
    if (i < 25600) {
        int icpos = i >> 5, ocl = i & 31;
        g_w2p[i] = pack2(w[ocl * 800 + icpos], w[(ocl + 32) * 800 + icpos]);
    }
}

// ============================================================================
// K1: conv1 + ternarize + BN + maxpool + relu. (proven)
// ============================================================================
__global__ __launch_bounds__(384) void k1_conv1(
    const float* __restrict__ x, const float* __restrict__ w,
    const float* __restrict__ bias, const float* __restrict__ bng,
    const float* __restrict__ bnb)
{
    __shared__ float s_in[784];
    __shared__ u64   s_w[400];
    __shared__ u64   s_b[16];
    __shared__ float s_ex[9504];
    __shared__ float s_red[64];

    const int tid = threadIdx.x;
    const int s = blockIdx.x;
    const int ocl = tid & 15;
    const int oy  = tid >> 4;

    const float* xin = x + s * 784;
    for (int i = tid; i < 784; i += 384) s_in[i] = xin[i];
    for (int i = tid; i < 400; i += 384) {
        int pos = i >> 4, oc2 = i & 15;
        s_w[i] = pack2(w[oc2 * 25 + pos], w[(oc2 + 16) * 25 + pos]);
    }
    if (tid < 16) s_b[tid] = pack2(bias[tid], bias[tid + 16]);
    __syncthreads();

    u64 acc[24];
    {
        const u64 bb = s_b[ocl];
        #pragma unroll
        for (int p = 0; p < 24; p++) acc[p] = bb;
    }

    #pragma unroll
    for (int ky = 0; ky < 5; ky++) {
        const float* rp = s_in + (oy + ky) * 28;
        u64 rp2[28];
        #pragma unroll
        for (int t = 0; t < 7; t++) {
            const float4 q = *(const float4*)(rp + t * 4);
            rp2[t * 4 + 0] = pack2(q.x, q.x);
            rp2[t * 4 + 1] = pack2(q.y, q.y);
            rp2[t * 4 + 2] = pack2(q.z, q.z);
            rp2[t * 4 + 3] = pack2(q.w, q.w);
        }
        #pragma unroll
        for (int kx = 0; kx < 5; kx++) {
            const u64 wv = s_w[(ky * 5 + kx) * 16 + ocl];
            #pragma unroll
            for (int p = 0; p < 24; p++) FMA2(acc[p], rp2[p + kx], wv);
        }
    }

    float sa = 0.f;
    #pragma unroll
    for (int p = 0; p < 24; p++) {
        const float2 t = unpack2(acc[p]);
        sa += fabsf(t.x) + fabsf(t.y);
    }
    const float tot = block_reduce(sa, s_red, tid, 384);
    const float delta = 0.7f * tot / 18432.f;

    float ms = 0.f, ct = 0.f;
    #pragma unroll
    for (int p = 0; p < 24; p++) {
        const float2 t = unpack2(acc[p]);
        float a = fabsf(t.x); if (a > delta) { ms += a; ct += 1.f; }
        a = fabsf(t.y);       if (a > delta) { ms += a; ct += 1.f; }
    }
    const float2 mc = block_reduce2(ms, ct, s_red, tid, 384);
    const float alpha = mc.x / mc.y;

    const float g0 = bng[ocl] * BN_INV, b0 = bnb[ocl];
    const float g1 = bng[ocl + 16] * BN_INV, b1 = bnb[ocl + 16];

    #pragma unroll
    for (int p = 0; p < 12; p++) {
        const float2 ta = unpack2(acc[2 * p]);
        const float2 tb = unpack2(acc[2 * p + 1]);
        const float mlo = fmaxf(fmaf(ternv(ta.x, delta, alpha), g0, b0),
                                fmaf(ternv(tb.x, delta, alpha), g0, b0));
        const float mhi = fmaxf(fmaf(ternv(ta.y, delta, alpha), g1, b1),
                                fmaf(ternv(tb.y, delta, alpha), g1, b1));
        s_ex[(oy * 12 + p) * 33 + ocl]      = mlo;
        s_ex[(oy * 12 + p) * 33 + ocl + 16] = mhi;
    }
    __syncthreads();

    for (int i = tid; i < 4608; i += 384) {
        const int oc = i / 144, r = i % 144, py = r / 12, px = r % 12;
        const float m = fmaxf(s_ex[((2 * py) * 12 + px) * 33 + oc],
                              s_ex[((2 * py + 1) * 12 + px) * 33 + oc]);
        g_h1[s * 4608 + i] = fmaxf(m, 0.f);
    }
}

// ============================================================================
// K2: conv2 fused. PERSISTENT, 256 threads, input prefetch pipeline. (proven)
// ============================================================================
#define K2_SMEM (25600 * 8 + 4608 * 4 + 2080 * 4 + 48 * 4)

__global__ __launch_bounds__(256) void k2_conv2(
    const float* __restrict__ bias, const float* __restrict__ bng,
    const float* __restrict__ bnb)
{
    extern __shared__ char smraw[];
    u64*   s_w    = (u64*)smraw;
    float* s_in   = (float*)(smraw + 25600 * 8);
    float* s_ex   = s_in + 4608;
    float* s_redA = s_ex + 2080;
    float* s_redB = s_redA + 16;
    float* s_redC = s_redB + 16;

    const int tid = threadIdx.x;
    const int lane = tid & 31, wid = tid >> 5;
    const int ocl = tid & 31;
    const int oy  = tid >> 5;

    for (int i = tid; i < 25600; i += 256) s_w[i] = g_w2p[i];

    const u64 bb = pack2(bias[ocl], bias[ocl + 32]);
    const float g0 = bng[ocl] * BN_INV, b0 = bnb[ocl];
    const float g1 = bng[ocl + 32] * BN_INV, b1 = bnb[ocl + 32];

    {
        const float4* hin = (const float4*)(g_h1 + blockIdx.x * 4608);
        float4* si4 = (float4*)s_in;
        for (int i = tid; i < 1152; i += 256) si4[i] = hin[i];
    }
    __syncthreads();

    for (int s = blockIdx.x; s < BATCH; s += gridDim.x) {
        const int sn = s + gridDim.x;
        const bool hn = sn < BATCH;
        float4 pf0, pf1, pf2, pf3, pf4;
        if (hn) {
            const float4* nin = (const float4*)(g_h1 + (size_t)sn * 4608);
            pf0 = nin[tid];       pf1 = nin[tid + 256];
            pf2 = nin[tid + 512]; pf3 = nin[tid + 768];
            if (tid < 128) pf4 = nin[tid + 1024];
        }

        u64 acc[8];
        #pragma unroll
        for (int j = 0; j < 8; j++) acc[j] = bb;

        for (int ic = 0; ic < 32; ic++) {
            #pragma unroll
            for (int ky = 0; ky < 5; ky++) {
                const float* rp = s_in + ic * 144 + (oy + ky) * 12;
                const float4 q0 = *(const float4*)(rp);
                const float4 q1 = *(const float4*)(rp + 4);
                const float4 q2 = *(const float4*)(rp + 8);
                u64 rw[12];
                rw[0]  = pack2(q0.x, q0.x); rw[1]  = pack2(q0.y, q0.y);
                rw[2]  = pack2(q0.z, q0.z); rw[3]  = pack2(q0.w, q0.w);
                rw[4]  = pack2(q1.x, q1.x); rw[5]  = pack2(q1.y, q1.y);
                rw[6]  = pack2(q1.z, q1.z); rw[7]  = pack2(q1.w, q1.w);
                rw[8]  = pack2(q2.x, q2.x); rw[9]  = pack2(q2.y, q2.y);
                rw[10] = pack2(q2.z, q2.z); rw[11] = pack2(q2.w, q2.w);
                const u64* wrow = s_w + (ic * 25 + ky * 5) * 32 + ocl;
                #pragma unroll
                for (int kx = 0; kx < 5; kx++) {
                    const u64 wv = wrow[kx * 32];
                    #pragma unroll
                    for (int j = 0; j < 8; j++) FMA2(acc[j], rw[j + kx], wv);
                }
            }
        }

        float sa = 0.f;
        #pragma unroll
        for (int j = 0; j < 8; j++) {
            const float2 t = unpack2(acc[j]);
            sa += fabsf(t.x) + fabsf(t.y);
        }
        #pragma unroll
        for (int o = 16; o > 0; o >>= 1) sa += __shfl_down_sync(0xffffffffu, sa, o);
        if (lane == 0) s_redA[wid] = sa;
        __syncthreads();   // (A)

        if (hn) {
            float4* si4 = (float4*)s_in;
            si4[tid] = pf0;       si4[tid + 256] = pf1;
            si4[tid + 512] = pf2; si4[tid + 768] = pf3;
            if (tid < 128) si4[tid + 1024] = pf4;
        }

        float tot = 0.f;
        #pragma unroll
        for (int wk = 0; wk < 8; wk++) tot += s_redA[wk];
        const float delta = 0.7f * tot / 4096.f;

        float ms = 0.f, ct = 0.f;
        #pragma unroll
        for (int j = 0; j < 8; j++) {
            const float2 t = unpack2(acc[j]);
            float a = fabsf(t.x); if (a > delta) { ms += a; ct += 1.f; }
            a = fabsf(t.y);       if (a > delta) { ms += a; ct += 1.f; }
        }
        #pragma unroll
        for (int o = 16; o > 0; o >>= 1) {
            ms += __shfl_down_sync(0xffffffffu, ms, o);
            ct += __shfl_down_sync(0xffffffffu, ct, o);
        }
        if (lane == 0) { s_redB[wid] = ms; s_redC[wid] = ct; }
        __syncthreads();   // (B)
        float mtot = 0.f, ctot = 0.f;
        #pragma unroll
        for (int wk = 0; wk < 8; wk++) { mtot += s_redB[wk]; ctot += s_redC[wk]; }
        const float alpha = mtot / ctot;

        #pragma unroll
        for (int p = 0; p < 4; p++) {
            const float2 ta = unpack2(acc[2 * p]);
            const float2 tb = unpack2(acc[2 * p + 1]);
            const float mlo = fmaxf(fmaf(ternv(ta.x, delta, alpha), g0, b0),
                                    fmaf(ternv(tb.x, delta, alpha), g0, b0));
            const float mhi = fmaxf(fmaf(ternv(ta.y, delta, alpha), g1, b1),
                                    fmaf(ternv(tb.y, delta, alpha), g1, b1));
            s_ex[(oy * 4 + p) * 65 + ocl]      = mlo;
            s_ex[(oy * 4 + p) * 65 + ocl + 32] = mhi;
        }
        __syncthreads();   // (C)

        for (int i = tid; i < 1024; i += 256) {
            const int oc = i >> 4, r = i & 15, py = r >> 2, px = r & 3;
            const float m = fmaxf(s_ex[((2 * py) * 4 + px) * 65 + oc],
                                  s_ex[((2 * py + 1) * 4 + px) * 65 + oc]);
            g_h2[s * 1024 + i] = fmaxf(m, 0.f);
        }
    }
}

// ============================================================================
// K3: fc1 GEMM. 128x64 tile, 256 threads, 8m x 4n, acc paired over m.
// Ktile=32: half the barriers of r6; double-buffered dynamic smem (51.2KB).
// Grid 8x16 = 128 CTAs (1 wave).
// ============================================================================
#define K3_TK 32
#define K3_ASTRIDE 132
#define K3_SMEM ((2 * K3_TK * K3_ASTRIDE + 2 * K3_TK * 68) * 4)

__global__ __launch_bounds__(256) void k3_fc1(
    const float* __restrict__ Wf, const float* __restrict__ bf)
{
    extern __shared__ float k3sm[];
    float* As = k3sm;                          // [2][32][132]
    float* Bs = k3sm + 2 * K3_TK * K3_ASTRIDE; // [2][32][68]

    const int tid = threadIdx.x;
    const int tn = tid & 15;       // n = tn*4
    const int tm = tid >> 4;       // m = tm*8 (0..15)
    const int bn = blockIdx.x;     // 0..7
    const int bm = blockIdx.y;     // 0..15

    const float* Ap = g_h2 + (size_t)(bm * 128) * 1024;
    const float* Bp = Wf   + (size_t)(bn * 64) * 1024;

    const int lrA = tid >> 1;           // A row 0..127
    const int lkA = (tid & 1) * 16;     // k 0 or 16
    const int lrB = tid >> 2;           // B row 0..63
    const int lkB = (tid & 3) * 8;      // k 0,8,16,24

    u64 acc[4][4];   // [m-pair][n]
    #pragma unroll
    for (int i = 0; i < 4; i++)
        #pragma unroll
        for (int j = 0; j < 4; j++) acc[i][j] = 0ull;

    // prologue: tile 0
    {
        float4 a[4], b[2];
        #pragma unroll
        for (int j = 0; j < 4; j++) a[j] = *(const float4*)(Ap + lrA * 1024 + lkA + 4 * j);
        #pragma unroll
        for (int j = 0; j < 2; j++) b[j] = *(const float4*)(Bp + lrB * 1024 + lkB + 4 * j);
        #pragma unroll
        for (int j = 0; j < 4; j++) {
            As[(lkA + 4 * j + 0) * K3_ASTRIDE + lrA] = a[j].x;
            As[(lkA + 4 * j + 1) * K3_ASTRIDE + lrA] = a[j].y;
            As[(lkA + 4 * j + 2) * K3_ASTRIDE + lrA] = a[j].z;
            As[(lkA + 4 * j + 3) * K3_ASTRIDE + lrA] = a[j].w;
        }
        #pragma unroll
        for (int j = 0; j < 2; j++) {
            Bs[(lkB + 4 * j + 0) * 68 + lrB] = b[j].x;
            Bs[(lkB + 4 * j + 1) * 68 + lrB] = b[j].y;
            Bs[(lkB + 4 * j + 2) * 68 + lrB] = b[j].z;
            Bs[(lkB + 4 * j + 3) * 68 + lrB] = b[j].w;
        }
    }
    __syncthreads();

    for (int t = 0; t < 32; t++) {
        const int cur = t & 1;
        const float* Acur = As + cur * K3_TK * K3_ASTRIDE;
        const float* Bcur = Bs + cur * K3_TK * 68;
        float4 an[4], bn2[2];
        if (t < 31) {
            #pragma unroll
            for (int j = 0; j < 4; j++)
                an[j] = *(const float4*)(Ap + lrA * 1024 + (t + 1) * K3_TK + lkA + 4 * j);
            #pragma unroll
            for (int j = 0; j < 2; j++)
                bn2[j] = *(const float4*)(Bp + lrB * 1024 + (t + 1) * K3_TK + lkB + 4 * j);
        }
        #pragma unroll
        for (int kk = 0; kk < K3_TK; kk++) {
            const ulonglong2 am01 = *(const ulonglong2*)&Acur[kk * K3_ASTRIDE + tm * 8];
            const ulonglong2 am23 = *(const ulonglong2*)&Acur[kk * K3_ASTRIDE + tm * 8 + 4];
            const float4 bv = *(const float4*)&Bcur[kk * 68 + tn * 4];
            const u64 b0 = pack2(bv.x, bv.x);
            const u64 b1 = pack2(bv.y, bv.y);
            const u64 b2 = pack2(bv.z, bv.z);
            const u64 b3 = pack2(bv.w, bv.w);
            FMA2(acc[0][0], am01.x, b0); FMA2(acc[0][1], am01.x, b1);
            FMA2(acc[0][2], am01.x, b2); FMA2(acc[0][3], am01.x, b3);
            FMA2(acc[1][0], am01.y, b0); FMA2(acc[1][1], am01.y, b1);
            FMA2(acc[1][2], am01.y, b2); FMA2(acc[1][3], am01.y, b3);
            FMA2(acc[2][0], am23.x, b0); FMA2(acc[2][1], am23.x, b1);
            FMA2(acc[2][2], am23.x, b2); FMA2(acc[2][3], am23.x, b3);
            FMA2(acc[3][0], am23.y, b0); FMA2(acc[3][1], am23.y, b1);
            FMA2(acc[3][2], am23.y, b2); FMA2(acc[3][3], am23.y, b3);
        }
        if (t < 31) {
            const int nxt = cur ^ 1;
            float* Anxt = As + nxt * K3_TK * K3_ASTRIDE;
            float* Bnxt = Bs + nxt * K3_TK * 68;
            #pragma unroll
            for (int j = 0; j < 4; j++) {
                Anxt[(lkA + 4 * j + 0) * K3_ASTRIDE + lrA] = an[j].x;
                Anxt[(lkA + 4 * j + 1) * K3_ASTRIDE + lrA] = an[j].y;
                Anxt[(lkA + 4 * j + 2) * K3_ASTRIDE + lrA] = an[j].z;
                Anxt[(lkA + 4 * j + 3) * K3_ASTRIDE + lrA] = an[j].w;
            }
            #pragma unroll
            for (int j = 0; j < 2; j++) {
                Bnxt[(lkB + 4 * j + 0) * 68 + lrB] = bn2[j].x;
                Bnxt[(lkB + 4 * j + 1) * 68 + lrB] = bn2[j].y;
                Bnxt[(lkB + 4 * j + 2) * 68 + lrB] = bn2[j].z;
                Bnxt[(lkB + 4 * j + 3) * 68 + lrB] = bn2[j].w;
            }
        }
        __syncthreads();
    }

    const int n0 = bn * 64 + tn * 4;
    const float4 bia = *(const float4*)(bf + n0);
    #pragma unroll
    for (int i = 0; i < 4; i++) {
        const float2 r0 = unpack2(acc[i][0]);
        const float2 r1 = unpack2(acc[i][1]);
        const float2 r2 = unpack2(acc[i][2]);
        const float2 r3 = unpack2(acc[i][3]);
        const int m = bm * 128 + tm * 8 + 2 * i;
        float4 oe, oo;
        oe.x = r0.x + bia.x; oe.y = r1.x + bia.y;
        oe.z = r2.x + bia.z; oe.w = r3.x + bia.w;
        oo.x = r0.y + bia.x; oo.y = r1.y + bia.y;
        oo.z = r2.y + bia.z; oo.w = r3.y + bia.w;
        *(float4*)(g_fc1 + (size_t)m * 512 + n0)       = oe;
        *(float4*)(g_fc1 + (size_t)(m + 1) * 512 + n0) = oo;
    }
}

// ============================================================================
// K4: ternarize(512)+relu + fc2 + ternarize(10). 1 warp/sample. (proven)
// ============================================================================
__global__ __launch_bounds__(256) void k4_fc2(
    const float* __restrict__ W2, const float* __restrict__ b2,
    float* __restrict__ out)
{
    __shared__ float s_w2[5120];
    __shared__ float s_b2[10];

    const int tid = threadIdx.x;
    for (int i = tid; i < 5120; i += 256) s_w2[i] = W2[i];
    if (tid < 10) s_b2[tid] = b2[tid];
    __syncthreads();

    const int lane = tid & 31, warp = tid >> 5;
    const int s = blockIdx.x * 8 + warp;
    const float* hr = g_fc1 + (size_t)s * 512;

    float h[16];
    #pragma unroll
    for (int k = 0; k < 16; k++) h[k] = hr[lane + 32 * k];

    float sa = 0.f;
    #pragma unroll
    for (int k = 0; k < 16; k++) sa += fabsf(h[k]);
    #pragma unroll
    for (int o = 16; o > 0; o >>= 1) sa += __shfl_xor_sync(0xffffffffu, sa, o);
    const float delta = 0.7f * sa / 512.f;

    float ms = 0.f, ct = 0.f;
    #pragma unroll
    for (int k = 0; k < 16; k++) {
        const float a = fabsf(h[k]);
        if (a > delta) { ms += a; ct += 1.f; }
    }
    #pragma unroll
    for (int o = 16; o > 0; o >>= 1) {
        ms += __shfl_xor_sync(0xffffffffu, ms, o);
        ct += __shfl_xor_sync(0xffffffffu, ct, o);
    }
    const float alpha = ms / ct;

    #pragma unroll
    for (int k = 0; k < 16; k++) h[k] = fmaxf(ternv(h[k], delta, alpha), 0.f);

    float pj[10];
    #pragma unroll
    for (int j = 0; j < 10; j++) {
        float p = 0.f;
        #pragma unroll
        for (int k = 0; k < 16; k++)
            p = fmaf(h[k], s_w2[j * 512 + lane + 32 * k], p);
        #pragma unroll
        for (int o = 16; o > 0; o >>= 1) p += __shfl_xor_sync(0xffffffffu, p, o);
        pj[j] = p + s_b2[j];
    }

    float sa2 = 0.f;
    #pragma unroll
    for (int j = 0; j < 10; j++) sa2 += fabsf(pj[j]);
    const float d2 = 0.7f * sa2 / 10.f;
    float ms2 = 0.f, c2 = 0.f;
    #pragma unroll
    for (int j = 0; j < 10; j++) {
        const float a = fabsf(pj[j]);
        if (a > d2) { ms2 += a; c2 += 1.f; }
    }
    const float al2 = ms2 / c2;

    if (lane < 10) {
        float v = 0.f;
        #pragma unroll
        for (int j = 0; j < 10; j++) if (lane == j) v = pj[j];
        out[(size_t)s * 10 + lane] = (v > d2) ? al2 : ((v < -d2) ? -al2 : 0.f);
    }
}

// ============================================================================
extern "C" void kernel_launch(void* const* d_in, const int* in_sizes, int n_in,
                              void* d_out, int out_size)
{
    const float* x       = (const float*)d_in[0];
    const float* conv1_w = (const float*)d_in[1];
    const float* conv1_b = (const float*)d_in[2];
    const float* bn1_g   = (const float*)d_in[3];
    const float* bn1_b   = (const float*)d_in[4];
    const float* conv2_w = (const float*)d_in[5];
    const float* conv2_b = (const float*)d_in[6];
    const float* bn2_g   = (const float*)d_in[7];
    const float* bn2_b   = (const float*)d_in[8];
    const float* fc1_w   = (const float*)d_in[9];
    const float* fc1_b   = (const float*)d_in[10];
    const float* fc2_w   = (const float*)d_in[11];
    const float* fc2_b   = (const float*)d_in[12];
    float* out = (float*)d_out;

    int nsm = 148;
    cudaDeviceGetAttribute(&nsm, cudaDevAttrMultiProcessorCount, 0);
    if (nsm <= 0) nsm = 148;

    cudaFuncSetAttribute(k2_conv2, cudaFuncAttributeMaxDynamicSharedMemorySize, K2_SMEM);
    cudaFuncSetAttribute(k3_fc1,   cudaFuncAttributeMaxDynamicSharedMemorySize, K3_SMEM);

    k0_pack_w2<<<100, 256>>>(conv2_w);
    k1_conv1<<<BATCH, 384>>>(x, conv1_w, conv1_b, bn1_g, bn1_b);
    k2_conv2<<<nsm, 256, K2_SMEM>>>(conv2_b, bn2_g, bn2_b);
    k3_fc1<<<dim3(8, 16), 256, K3_SMEM>>>(fc1_w, fc1_b);
    k4_fc2<<<256, 256>>>(fc2_w, fc2_b, out);
}